// round 3
// baseline (speedup 1.0000x reference)
#include <cuda_runtime.h>

// ---------------------------------------------------------------------------
// TTLayer: out = x @ W + bias, with W the dense 4096x4096 realization of the
// 4-core TT operator. Strategy:
//   1) G01[(i0,i1),(o0,o1),r2] = sum_r1 core0[0,i0,o0,r1]*core1[r1,i1,o1,r2]
//   2) G23[r2,(i2,i3),(o2,o3)] = sum_r3 core2[r2,i2,o2,r3]*core3[r3,i3,o3,0]
//   3) W[(P*64+S),(Q*64+T)]    = sum_r2 G01[P,Q,r2]*G23[r2,S,T]
//   4) out = x @ W + bias      (1024 x 4096 x 4096 SGEMM)
// ---------------------------------------------------------------------------

#define N_DIM 4096
#define B_DIM 1024
#define R 64

static __device__ float g_G01[64 * 64 * 64];   // [(P*64+Q)*64 + r2]
static __device__ float g_G23[64 * 64 * 64];   // [r2*4096 + S*64 + T]
static __device__ float g_W[(size_t)N_DIM * N_DIM];  // [n*4096 + m]

// ---------------------------------------------------------------------------
// G01[P,Q,r2] = sum_r1 core0[(i0*8+o0)*64 + r1] * core1[r1*4096 + (i1*8+o1)*64 + r2]
// ---------------------------------------------------------------------------
__global__ void build_G01_kernel(const float* __restrict__ core0,
                                 const float* __restrict__ core1) {
    int idx = blockIdx.x * blockDim.x + threadIdx.x;   // 262144
    int r2 = idx & 63;
    int pq = idx >> 6;
    int Q = pq & 63, P = pq >> 6;
    int i0 = P >> 3, i1 = P & 7;
    int o0 = Q >> 3, o1 = Q & 7;
    const float* c0 = core0 + (i0 * 8 + o0) * 64;          // + r1
    const float* c1 = core1 + (i1 * 8 + o1) * 64 + r2;     // + r1*4096
    float acc = 0.f;
#pragma unroll 16
    for (int r1 = 0; r1 < 64; ++r1)
        acc = fmaf(c0[r1], c1[r1 * 4096], acc);
    g_G01[idx] = acc;
}

// ---------------------------------------------------------------------------
// G23[r2,S,T] = sum_r3 core2[((r2*8+i2)*8+o2)*64 + r3] * core3[r3*64 + i3*8 + o3]
// ---------------------------------------------------------------------------
__global__ void build_G23_kernel(const float* __restrict__ core2,
                                 const float* __restrict__ core3) {
    int idx = blockIdx.x * blockDim.x + threadIdx.x;   // 262144: r2*4096 + S*64 + T
    int T = idx & 63;
    int S = (idx >> 6) & 63;
    int r2 = idx >> 12;
    int i2 = S >> 3, i3 = S & 7;
    int o2 = T >> 3, o3 = T & 7;
    const float* c2 = core2 + ((r2 * 8 + i2) * 8 + o2) * 64;  // + r3
    const float* c3 = core3 + i3 * 8 + o3;                    // + r3*64
    float acc = 0.f;
#pragma unroll 16
    for (int r3 = 0; r3 < 64; ++r3)
        acc = fmaf(c2[r3], c3[r3 * 64], acc);
    g_G23[idx] = acc;
}

// ---------------------------------------------------------------------------
// One block per (P,S). Produces W row n = P*64+S: W[n, Q*64+T] for all Q,T.
// ---------------------------------------------------------------------------
__global__ __launch_bounds__(256) void build_W_kernel() {
    // sAt[r2][Q] (stride 68 keeps float4 reads aligned), sB[r2][T]
    __shared__ float sAt[64 * 68];
    __shared__ float sB[64 * 64];

    int bx = blockIdx.x;           // 4096 blocks
    int P = bx >> 6, S = bx & 63;
    int tid = threadIdx.x;

    const float* gA = g_G01 + P * 4096;   // [(Q)*64 + r2]
    const float* gB = g_G23 + S * 64;     // [r2*4096 + T]

    for (int e = tid; e < 4096; e += 256) {
        int Q = e >> 6, r2 = e & 63;
        sAt[r2 * 68 + Q] = gA[e];         // transpose on store
        int r2b = e >> 6, T = e & 63;
        sB[e] = gB[r2b * 4096 + T];
    }
    __syncthreads();

    int Q0 = (tid >> 4) * 4;
    int T0 = (tid & 15) * 4;

    float acc[4][4];
#pragma unroll
    for (int q = 0; q < 4; ++q)
#pragma unroll
        for (int t = 0; t < 4; ++t) acc[q][t] = 0.f;

#pragma unroll 4
    for (int r2 = 0; r2 < 64; ++r2) {
        float4 a = *(const float4*)&sAt[r2 * 68 + Q0];
        float4 b = *(const float4*)&sB[r2 * 64 + T0];
        float ar[4] = {a.x, a.y, a.z, a.w};
        float br[4] = {b.x, b.y, b.z, b.w};
#pragma unroll
        for (int q = 0; q < 4; ++q)
#pragma unroll
            for (int t = 0; t < 4; ++t)
                acc[q][t] = fmaf(ar[q], br[t], acc[q][t]);
    }

    int n = P * 64 + S;
    float* wrow = g_W + (size_t)n * N_DIM;
#pragma unroll
    for (int q = 0; q < 4; ++q) {
        float4 v = make_float4(acc[q][0], acc[q][1], acc[q][2], acc[q][3]);
        *(float4*)&wrow[(Q0 + q) * 64 + T0] = v;
    }
}

// ---------------------------------------------------------------------------
// Main SGEMM: C[1024,4096] = A[1024,4096] * W[4096,4096] + bias
// 128x128 block tile, BK=8, 256 threads, 8x8 per-thread, double-buffered.
// ---------------------------------------------------------------------------
#define BM 128
#define BN 128
#define BK 8

__global__ __launch_bounds__(256, 2) void sgemm_bias_kernel(
    const float* __restrict__ A,     // x [1024, 4096]
    const float* __restrict__ bias,  // [4096]
    float* __restrict__ C)           // [1024, 4096]
{
    __shared__ float As[2][BK][BM];   // [k][m] (A transposed in smem)
    __shared__ float Bs[2][BK][BN];   // [k][n]

    const int K = N_DIM;
    const int N = N_DIM;

    int tid = threadIdx.x;
    int bm = blockIdx.y * BM;
    int bn = blockIdx.x * BN;

    // A tile loaders: 128 rows x 8 cols = 256 float4; one per thread
    int a_row = tid >> 1;              // 0..127
    int a_k4  = (tid & 1) * 4;         // 0 or 4
    // B tile loaders: 8 rows x 128 cols = 256 float4
    int b_k   = tid >> 5;              // 0..7
    int b_n4  = (tid & 31) * 4;        // 0..124

    const float* Aptr = A + (bm + a_row) * K + a_k4;
    const float* Bptr = g_W + (size_t)b_k * N + bn + b_n4;

    // Prologue: stage 0
    {
        float4 av = *(const float4*)Aptr;
        float4 bv = *(const float4*)Bptr;
        As[0][a_k4 + 0][a_row] = av.x;
        As[0][a_k4 + 1][a_row] = av.y;
        As[0][a_k4 + 2][a_row] = av.z;
        As[0][a_k4 + 3][a_row] = av.w;
        *(float4*)&Bs[0][b_k][b_n4] = bv;
    }
    __syncthreads();

    int tr = (tid >> 4) * 8;   // 0..120
    int tc = (tid & 15) * 8;   // 0..120

    float acc[8][8];
#pragma unroll
    for (int i = 0; i < 8; ++i)
#pragma unroll
        for (int j = 0; j < 8; ++j) acc[i][j] = 0.f;

    const int nk = K / BK;   // 512
    for (int kt = 0; kt < nk; ++kt) {
        int cur = kt & 1;
        int nxt = cur ^ 1;

        float4 pa, pb;
        bool has_next = (kt + 1) < nk;
        if (has_next) {
            pa = *(const float4*)(Aptr + (kt + 1) * BK);
            pb = *(const float4*)(Bptr + (size_t)(kt + 1) * BK * N);
        }

#pragma unroll
        for (int k = 0; k < BK; ++k) {
            float4 a0 = *(const float4*)&As[cur][k][tr];
            float4 a1 = *(const float4*)&As[cur][k][tr + 4];
            float4 b0 = *(const float4*)&Bs[cur][k][tc];
            float4 b1 = *(const float4*)&Bs[cur][k][tc + 4];
            float ar[8] = {a0.x, a0.y, a0.z, a0.w, a1.x, a1.y, a1.z, a1.w};
            float br[8] = {b0.x, b0.y, b0.z, b0.w, b1.x, b1.y, b1.z, b1.w};
#pragma unroll
            for (int i = 0; i < 8; ++i)
#pragma unroll
                for (int j = 0; j < 8; ++j)
                    acc[i][j] = fmaf(ar[i], br[j], acc[i][j]);
        }

        if (has_next) {
            As[nxt][a_k4 + 0][a_row] = pa.x;
            As[nxt][a_k4 + 1][a_row] = pa.y;
            As[nxt][a_k4 + 2][a_row] = pa.z;
            As[nxt][a_k4 + 3][a_row] = pa.w;
            *(float4*)&Bs[nxt][b_k][b_n4] = pb;
        }
        __syncthreads();
    }

    // Epilogue: add bias, store
    int col = bn + tc;
    float4 bb0 = *(const float4*)&bias[col];
    float4 bb1 = *(const float4*)&bias[col + 4];
    float bj[8] = {bb0.x, bb0.y, bb0.z, bb0.w, bb1.x, bb1.y, bb1.z, bb1.w};

#pragma unroll
    for (int i = 0; i < 8; ++i) {
        int row = bm + tr + i;
        float4 v0 = make_float4(acc[i][0] + bj[0], acc[i][1] + bj[1],
                                acc[i][2] + bj[2], acc[i][3] + bj[3]);
        float4 v1 = make_float4(acc[i][4] + bj[4], acc[i][5] + bj[5],
                                acc[i][6] + bj[6], acc[i][7] + bj[7]);
        *(float4*)&C[(size_t)row * N + col] = v0;
        *(float4*)&C[(size_t)row * N + col + 4] = v1;
    }
}

// ---------------------------------------------------------------------------
extern "C" void kernel_launch(void* const* d_in, const int* in_sizes, int n_in,
                              void* d_out, int out_size) {
    const float* x     = (const float*)d_in[0];  // [1024, 4096]
    const float* core0 = (const float*)d_in[1];  // (1,8,8,64)
    const float* core1 = (const float*)d_in[2];  // (64,8,8,64)
    const float* core2 = (const float*)d_in[3];  // (64,8,8,64)
    const float* core3 = (const float*)d_in[4];  // (64,8,8,1)
    const float* bias  = (const float*)d_in[5];  // [4096]
    float* out = (float*)d_out;                  // [1024, 4096]

    build_G01_kernel<<<1024, 256>>>(core0, core1);
    build_G23_kernel<<<1024, 256>>>(core2, core3);
    build_W_kernel<<<4096, 256>>>();

    dim3 grid(N_DIM / BN, B_DIM / BM);   // (32, 8) = 256 blocks
    sgemm_bias_kernel<<<grid, 256>>>(x, bias, out);
}

// round 7
// speedup vs baseline: 2.0501x; 2.0501x over previous
#include <cuda_runtime.h>
#include <cuda_bf16.h>
#include <cstdint>

// ===========================================================================
// TTLayer = x @ W + bias with W the dense TT realization.
//   Builders (fp32): G01t[Q][r2][P], G23t[T][r2][S], Wt[out][in] -> bf16 hi/lo
//   x -> bf16 hi/lo
//   Apply: mma.sync m16n8k16 bf16, D += Ah*Bh + Ah*Bl + Al*Bh  (f32 accum)
// ===========================================================================

#define N_DIM 4096
#define B_DIM 1024

static __device__ float         g_G01t[64 * 64 * 64];        // [Q][r2][P]
static __device__ float         g_G23t[64 * 64 * 64];        // [T][r2][S]
static __device__ __nv_bfloat16 g_xh[(size_t)B_DIM * N_DIM];
static __device__ __nv_bfloat16 g_xl[(size_t)B_DIM * N_DIM];
static __device__ __nv_bfloat16 g_wh[(size_t)N_DIM * N_DIM]; // Wt hi [out][in]
static __device__ __nv_bfloat16 g_wl[(size_t)N_DIM * N_DIM]; // Wt lo

// ---------------------------------------------------------------------------
__device__ __forceinline__ uint32_t smem_u32(const void* p) {
    uint32_t a;
    asm("{ .reg .u64 t; cvta.to.shared.u64 t, %1; cvt.u32.u64 %0, t; }"
        : "=r"(a) : "l"(p));
    return a;
}
__device__ __forceinline__ void cp_async16(uint32_t dst, const void* src) {
    asm volatile("cp.async.cg.shared.global [%0], [%1], 16;\n" :: "r"(dst), "l"(src));
}
#define CP_COMMIT() asm volatile("cp.async.commit_group;\n" ::: "memory")
#define CP_WAIT1()  asm volatile("cp.async.wait_group 1;\n" ::: "memory")
#define CP_WAIT0()  asm volatile("cp.async.wait_group 0;\n" ::: "memory")

#define LDSM_X4(r, addr) \
    asm volatile("ldmatrix.sync.aligned.m8n8.x4.shared.b16 {%0,%1,%2,%3}, [%4];" \
                 : "=r"((r)[0]), "=r"((r)[1]), "=r"((r)[2]), "=r"((r)[3]) : "r"(addr))
#define LDSM_X2(r, addr) \
    asm volatile("ldmatrix.sync.aligned.m8n8.x2.shared.b16 {%0,%1}, [%2];" \
                 : "=r"((r)[0]), "=r"((r)[1]) : "r"(addr))

#define MMA16816(d, a, b) \
    asm volatile("mma.sync.aligned.m16n8k16.row.col.f32.bf16.bf16.f32 " \
                 "{%0,%1,%2,%3}, {%4,%5,%6,%7}, {%8,%9}, {%0,%1,%2,%3};" \
                 : "+f"((d)[0]), "+f"((d)[1]), "+f"((d)[2]), "+f"((d)[3]) \
                 : "r"((a)[0]), "r"((a)[1]), "r"((a)[2]), "r"((a)[3]), \
                   "r"((b)[0]), "r"((b)[1]))

// ---------------------------------------------------------------------------
// Builders (unchanged math from the 927us-passing version, transposed layout)
// ---------------------------------------------------------------------------
__global__ void build_G01t_kernel(const float* __restrict__ core0,
                                  const float* __restrict__ core1) {
    int idx = blockIdx.x * blockDim.x + threadIdx.x;   // Q*4096 + r2*64 + P
    int P = idx & 63;
    int r2 = (idx >> 6) & 63;
    int Q = idx >> 12;
    int i0 = P >> 3, i1 = P & 7;
    int o0 = Q >> 3, o1 = Q & 7;
    const float* c0 = core0 + (i0 * 8 + o0) * 64;
    const float* c1 = core1 + (i1 * 8 + o1) * 64 + r2;
    float acc = 0.f;
#pragma unroll 16
    for (int r1 = 0; r1 < 64; ++r1)
        acc = fmaf(c0[r1], c1[r1 * 4096], acc);
    g_G01t[idx] = acc;
}

__global__ void build_G23t_kernel(const float* __restrict__ core2,
                                  const float* __restrict__ core3) {
    int idx = blockIdx.x * blockDim.x + threadIdx.x;   // T*4096 + r2*64 + S
    int S = idx & 63;
    int r2 = (idx >> 6) & 63;
    int T = idx >> 12;
    int i2 = S >> 3, i3 = S & 7;
    int o2 = T >> 3, o3 = T & 7;
    const float* c2 = core2 + ((r2 * 8 + i2) * 8 + o2) * 64;
    const float* c3 = core3 + i3 * 8 + o3;
    float acc = 0.f;
#pragma unroll 16
    for (int r3 = 0; r3 < 64; ++r3)
        acc = fmaf(c2[r3], c3[r3 * 64], acc);
    g_G23t[idx] = acc;
}

__global__ __launch_bounds__(256) void build_Wt_kernel() {
    __shared__ float sA[64 * 64];   // [r2][P]
    __shared__ float sB[64 * 64];   // [r2][S]
    int bx = blockIdx.x;            // 4096
    int Q = bx >> 6, T = bx & 63;
    int tid = threadIdx.x;

    const float* gA = g_G01t + Q * 4096;
    const float* gB = g_G23t + T * 4096;
    for (int e = tid; e < 4096; e += 256) { sA[e] = gA[e]; sB[e] = gB[e]; }
    __syncthreads();

    int P0 = (tid >> 4) * 4;
    int S0 = (tid & 15) * 4;
    float acc[4][4];
#pragma unroll
    for (int p = 0; p < 4; ++p)
#pragma unroll
        for (int s = 0; s < 4; ++s) acc[p][s] = 0.f;

#pragma unroll 4
    for (int r2 = 0; r2 < 64; ++r2) {
        float4 a = *(const float4*)&sA[r2 * 64 + P0];
        float4 b = *(const float4*)&sB[r2 * 64 + S0];
        float ar[4] = {a.x, a.y, a.z, a.w};
        float br[4] = {b.x, b.y, b.z, b.w};
#pragma unroll
        for (int p = 0; p < 4; ++p)
#pragma unroll
            for (int s = 0; s < 4; ++s)
                acc[p][s] = fmaf(ar[p], br[s], acc[p][s]);
    }

    size_t rowbase = (size_t)(Q * 64 + T) * N_DIM;
#pragma unroll
    for (int p = 0; p < 4; ++p) {
        __nv_bfloat16 hi[4], lo[4];
#pragma unroll
        for (int s = 0; s < 4; ++s) {
            float w = acc[p][s];
            hi[s] = __float2bfloat16(w);
            lo[s] = __float2bfloat16(w - __bfloat162float(hi[s]));
        }
        size_t off = rowbase + (P0 + p) * 64 + S0;
        *(uint2*)&g_wh[off] = *(uint2*)hi;
        *(uint2*)&g_wl[off] = *(uint2*)lo;
    }
}

__global__ void convert_x_kernel(const float* __restrict__ x) {
    int i4 = (blockIdx.x * blockDim.x + threadIdx.x) * 4;
    float4 v = *(const float4*)(x + i4);
    float f[4] = {v.x, v.y, v.z, v.w};
    __nv_bfloat16 hi[4], lo[4];
#pragma unroll
    for (int j = 0; j < 4; ++j) {
        hi[j] = __float2bfloat16(f[j]);
        lo[j] = __float2bfloat16(f[j] - __bfloat162float(hi[j]));
    }
    *(uint2*)&g_xh[i4] = *(uint2*)hi;
    *(uint2*)&g_xl[i4] = *(uint2*)lo;
}

// ---------------------------------------------------------------------------
// Apply GEMM: out[1024,4096] = x * Wt^T + bias via mma.sync bf16.
// CTA tile 128x256, BK=32, 2 stages, 256 threads, warp tile 64x64.
// ---------------------------------------------------------------------------
#define TM 128
#define TN 256
#define BKQ 32
#define NKCH (N_DIM / BKQ)           // 128
#define RS 40                        // smem row stride in bf16 (80 B, conflict-free)
#define A_DT_BYTES (TM * RS * 2)     // 10240
#define B_DT_BYTES (TN * RS * 2)     // 20480
#define OFF_AH 0
#define OFF_AL (A_DT_BYTES)
#define OFF_BH (2 * A_DT_BYTES)
#define OFF_BL (2 * A_DT_BYTES + B_DT_BYTES)
#define STAGE_BYTES (2 * A_DT_BYTES + 2 * B_DT_BYTES)   // 61440
#define SM_TOTAL (2 * STAGE_BYTES)                      // 122880

__device__ __forceinline__ void load_stage(uint32_t st, int bm, int bn, int k0, int tid) {
    // A: 128 rows x 4 chunks(16B) per dtype -> 512 chunks, 2/thread
#pragma unroll
    for (int j = 0; j < 2; ++j) {
        int c = tid + j * 256;
        int row = c >> 2, cc = c & 3;
        uint32_t so = row * (RS * 2) + cc * 16;
        size_t go = (size_t)(bm + row) * N_DIM + k0 + cc * 8;
        cp_async16(st + OFF_AH + so, g_xh + go);
        cp_async16(st + OFF_AL + so, g_xl + go);
    }
    // B: 256 rows x 4 chunks per dtype -> 1024 chunks, 4/thread
#pragma unroll
    for (int j = 0; j < 4; ++j) {
        int c = tid + j * 256;
        int row = c >> 2, cc = c & 3;
        uint32_t so = row * (RS * 2) + cc * 16;
        size_t go = (size_t)(bn + row) * N_DIM + k0 + cc * 8;
        cp_async16(st + OFF_BH + so, g_wh + go);
        cp_async16(st + OFF_BL + so, g_wl + go);
    }
}

__global__ __launch_bounds__(256, 1) void tt_gemm_kernel(
    const float* __restrict__ bias, float* __restrict__ out)
{
    extern __shared__ char smem[];
    uint32_t sb = smem_u32(smem);

    int tid = threadIdx.x;
    int lane = tid & 31;
    int wid = tid >> 5;
    int warp_m = wid & 1;        // 0..1 -> 64-row slab
    int warp_n = wid >> 1;       // 0..3 -> 64-col slab
    int bn = blockIdx.x * TN;
    int bm = blockIdx.y * TM;

    uint32_t stage[2] = {sb, sb + STAGE_BYTES};

    load_stage(stage[0], bm, bn, 0, tid);
    CP_COMMIT();
    load_stage(stage[1], bm, bn, BKQ, tid);
    CP_COMMIT();

    float acc[4][8][4];
#pragma unroll
    for (int mf = 0; mf < 4; ++mf)
#pragma unroll
        for (int nf = 0; nf < 8; ++nf)
#pragma unroll
            for (int e = 0; e < 4; ++e) acc[mf][nf][e] = 0.f;

    // ldmatrix base offsets (within a stage)
    uint32_t aoff = (warp_m * 64 + (lane & 15)) * (RS * 2) + (lane >> 4) * 16;
    uint32_t boff = (warp_n * 64 + (lane & 7)) * (RS * 2) + ((lane >> 3) & 1) * 16;

    for (int kt = 0; kt < NKCH; ++kt) {
        uint32_t st = stage[kt & 1];
        CP_WAIT1();
        __syncthreads();

        uint32_t aH = st + OFF_AH + aoff;
        uint32_t aL = st + OFF_AL + aoff;
        uint32_t bH = st + OFF_BH + boff;
        uint32_t bL = st + OFF_BL + boff;

#pragma unroll
        for (int ks = 0; ks < 2; ++ks) {
            uint32_t ko = ks * 32;   // 16 bf16 = 32 bytes
            uint32_t ah[4][4], al[4][4];
#pragma unroll
            for (int mf = 0; mf < 4; ++mf) {
                LDSM_X4(ah[mf], aH + mf * 16 * (RS * 2) + ko);
                LDSM_X4(al[mf], aL + mf * 16 * (RS * 2) + ko);
            }
#pragma unroll
            for (int nf = 0; nf < 8; ++nf) {
                uint32_t bh[2], bl[2];
                LDSM_X2(bh, bH + nf * 8 * (RS * 2) + ko);
                LDSM_X2(bl, bL + nf * 8 * (RS * 2) + ko);
#pragma unroll
                for (int mf = 0; mf < 4; ++mf) {
                    MMA16816(acc[mf][nf], ah[mf], bh);
                    MMA16816(acc[mf][nf], ah[mf], bl);
                    MMA16816(acc[mf][nf], al[mf], bh);
                }
            }
        }

        __syncthreads();
        if (kt + 2 < NKCH)
            load_stage(stage[kt & 1], bm, bn, (kt + 2) * BKQ, tid);
        CP_COMMIT();
    }
    CP_WAIT0();

    // Epilogue: thread t of tile (mf,nf): rows r0,r0+8; cols c0,c0+1
#pragma unroll
    for (int nf = 0; nf < 8; ++nf) {
        int col = bn + warp_n * 64 + nf * 8 + (lane & 3) * 2;
        float2 bv = *(const float2*)&bias[col];
#pragma unroll
        for (int mf = 0; mf < 4; ++mf) {
            int r0 = bm + warp_m * 64 + mf * 16 + (lane >> 2);
            float2 v0 = make_float2(acc[mf][nf][0] + bv.x, acc[mf][nf][1] + bv.y);
            float2 v1 = make_float2(acc[mf][nf][2] + bv.x, acc[mf][nf][3] + bv.y);
            *(float2*)&out[(size_t)r0 * N_DIM + col] = v0;
            *(float2*)&out[(size_t)(r0 + 8) * N_DIM + col] = v1;
        }
    }
}

// ---------------------------------------------------------------------------
extern "C" void kernel_launch(void* const* d_in, const int* in_sizes, int n_in,
                              void* d_out, int out_size) {
    const float* x     = (const float*)d_in[0];
    const float* core0 = (const float*)d_in[1];
    const float* core1 = (const float*)d_in[2];
    const float* core2 = (const float*)d_in[3];
    const float* core3 = (const float*)d_in[4];
    const float* bias  = (const float*)d_in[5];
    float* out = (float*)d_out;

    cudaFuncSetAttribute(tt_gemm_kernel,
                         cudaFuncAttributeMaxDynamicSharedMemorySize, SM_TOTAL);

    build_G01t_kernel<<<1024, 256>>>(core0, core1);
    build_G23t_kernel<<<1024, 256>>>(core2, core3);
    build_Wt_kernel<<<4096, 256>>>();
    convert_x_kernel<<<4096, 256>>>(x);

    dim3 grid(N_DIM / TN, B_DIM / TM);   // (16, 8) = 128 CTAs
    tt_gemm_kernel<<<grid, 256, SM_TOTAL>>>(bias, out);
}

// round 9
// speedup vs baseline: 3.8566x; 1.8812x over previous
#include <cuda_runtime.h>
#include <cuda_fp16.h>
#include <cstdint>

// ===========================================================================
// TTLayer = x @ W + bias, W = dense TT realization, fp16 single-product MMA.
//   G01t[Q][r2][P], G23t[T][r2][S]  (fp32)
//   Wt[out][in] fp16,  x -> fp16
//   out = fp16 mma (f32 accum) + bias
// ===========================================================================

#define N_DIM 4096
#define B_DIM 1024

static __device__ float  g_G01t[64 * 64 * 64];          // [Q][r2][P]
static __device__ float  g_G23t[64 * 64 * 64];          // [T][r2][S]
static __device__ __half g_xh[(size_t)B_DIM * N_DIM];   // x fp16
static __device__ __half g_w[(size_t)N_DIM * N_DIM];    // Wt fp16 [out][in]

// ---------------------------------------------------------------------------
__device__ __forceinline__ uint32_t smem_u32(const void* p) {
    uint32_t a;
    asm("{ .reg .u64 t; cvta.to.shared.u64 t, %1; cvt.u32.u64 %0, t; }"
        : "=r"(a) : "l"(p));
    return a;
}
__device__ __forceinline__ void cp_async16(uint32_t dst, const void* src) {
    asm volatile("cp.async.cg.shared.global [%0], [%1], 16;\n" :: "r"(dst), "l"(src));
}
#define CP_COMMIT() asm volatile("cp.async.commit_group;\n" ::: "memory")
#define CP_WAIT1()  asm volatile("cp.async.wait_group 1;\n" ::: "memory")
#define CP_WAIT0()  asm volatile("cp.async.wait_group 0;\n" ::: "memory")

#define LDSM_X4(r, addr) \
    asm volatile("ldmatrix.sync.aligned.m8n8.x4.shared.b16 {%0,%1,%2,%3}, [%4];" \
                 : "=r"((r)[0]), "=r"((r)[1]), "=r"((r)[2]), "=r"((r)[3]) : "r"(addr))
#define LDSM_X2(r, addr) \
    asm volatile("ldmatrix.sync.aligned.m8n8.x2.shared.b16 {%0,%1}, [%2];" \
                 : "=r"((r)[0]), "=r"((r)[1]) : "r"(addr))

#define MMA16816(d, a, b) \
    asm volatile("mma.sync.aligned.m16n8k16.row.col.f32.f16.f16.f32 " \
                 "{%0,%1,%2,%3}, {%4,%5,%6,%7}, {%8,%9}, {%0,%1,%2,%3};" \
                 : "+f"((d)[0]), "+f"((d)[1]), "+f"((d)[2]), "+f"((d)[3]) \
                 : "r"((a)[0]), "r"((a)[1]), "r"((a)[2]), "r"((a)[3]), \
                   "r"((b)[0]), "r"((b)[1]))

// ---------------------------------------------------------------------------
// Builders
// ---------------------------------------------------------------------------
__global__ void build_G01t_kernel(const float* __restrict__ core0,
                                  const float* __restrict__ core1) {
    int idx = blockIdx.x * blockDim.x + threadIdx.x;   // Q*4096 + r2*64 + P
    int P = idx & 63;
    int r2 = (idx >> 6) & 63;
    int Q = idx >> 12;
    int i0 = P >> 3, i1 = P & 7;
    int o0 = Q >> 3, o1 = Q & 7;
    const float* c0 = core0 + (i0 * 8 + o0) * 64;
    const float* c1 = core1 + (i1 * 8 + o1) * 64 + r2;
    float acc = 0.f;
#pragma unroll 16
    for (int r1 = 0; r1 < 64; ++r1)
        acc = fmaf(c0[r1], c1[r1 * 4096], acc);
    g_G01t[idx] = acc;
}

__global__ void build_G23t_kernel(const float* __restrict__ core2,
                                  const float* __restrict__ core3) {
    int idx = blockIdx.x * blockDim.x + threadIdx.x;   // T*4096 + r2*64 + S
    int S = idx & 63;
    int r2 = (idx >> 6) & 63;
    int T = idx >> 12;
    int i2 = S >> 3, i3 = S & 7;
    int o2 = T >> 3, o3 = T & 7;
    const float* c2 = core2 + ((r2 * 8 + i2) * 8 + o2) * 64;
    const float* c3 = core3 + i3 * 8 + o3;
    float acc = 0.f;
#pragma unroll 16
    for (int r3 = 0; r3 < 64; ++r3)
        acc = fmaf(c2[r3], c3[r3 * 64], acc);
    g_G23t[idx] = acc;
}

// ---------------------------------------------------------------------------
// build_Wt v2: block = (Q, group of 4 T).  Grid 1024.
// Output rows n = Q*64 + Tg*4 + tl over all in = P*64 + S (fp16).
// Per thread: 8 (P) x 8 (S within one tl) outputs.
// smem: sA[64 r2][64 P] (16 KB) + sB[64 r2][4 tl * 64 S] (64 KB) dynamic.
// ---------------------------------------------------------------------------
__global__ __launch_bounds__(256) void build_Wt_kernel() {
    extern __shared__ float sw[];
    float* sA = sw;               // [r2*64 + P]
    float* sB = sw + 64 * 64;     // [r2*256 + tl*64 + S]

    int bx = blockIdx.x;          // 1024
    int Q = bx >> 4, Tg = bx & 15;
    int tid = threadIdx.x;

    const float* gA = g_G01t + Q * 4096;
    for (int e = tid; e < 4096; e += 256) sA[e] = gA[e];
    const float* gB = g_G23t + Tg * 4 * 4096;
    for (int e = tid; e < 16384; e += 256) {
        int tl = e >> 12, r2 = (e >> 6) & 63, S = e & 63;
        sB[r2 * 256 + tl * 64 + S] = gB[tl * 4096 + r2 * 64 + S];
    }
    __syncthreads();

    int p0 = (tid >> 5) * 8;      // P tile
    int c0 = (tid & 31) * 8;      // column tile within [tl*64+S]
    int tl = c0 >> 6, S0 = c0 & 63;

    float acc[8][8];
#pragma unroll
    for (int p = 0; p < 8; ++p)
#pragma unroll
        for (int s = 0; s < 8; ++s) acc[p][s] = 0.f;

#pragma unroll 2
    for (int r2 = 0; r2 < 64; ++r2) {
        float4 a0 = *(const float4*)&sA[r2 * 64 + p0];
        float4 a1 = *(const float4*)&sA[r2 * 64 + p0 + 4];
        float4 b0 = *(const float4*)&sB[r2 * 256 + c0];
        float4 b1 = *(const float4*)&sB[r2 * 256 + c0 + 4];
        float ar[8] = {a0.x, a0.y, a0.z, a0.w, a1.x, a1.y, a1.z, a1.w};
        float br[8] = {b0.x, b0.y, b0.z, b0.w, b1.x, b1.y, b1.z, b1.w};
#pragma unroll
        for (int p = 0; p < 8; ++p)
#pragma unroll
            for (int s = 0; s < 8; ++s)
                acc[p][s] = fmaf(ar[p], br[s], acc[p][s]);
    }

    int n = Q * 64 + Tg * 4 + tl;
    __half* wrow = g_w + (size_t)n * N_DIM;
#pragma unroll
    for (int p = 0; p < 8; ++p) {
        __half h[8];
#pragma unroll
        for (int s = 0; s < 8; ++s) h[s] = __float2half_rn(acc[p][s]);
        *(uint4*)&wrow[(p0 + p) * 64 + S0] = *(uint4*)h;
    }
}

__global__ void convert_x_kernel(const float* __restrict__ x) {
    int i4 = (blockIdx.x * blockDim.x + threadIdx.x) * 4;
    float4 v = *(const float4*)(x + i4);
    __half h[4] = {__float2half_rn(v.x), __float2half_rn(v.y),
                   __float2half_rn(v.z), __float2half_rn(v.w)};
    *(uint2*)&g_xh[i4] = *(uint2*)h;
}

// ---------------------------------------------------------------------------
// Apply GEMM: out[1024,4096] = x * Wt^T + bias (fp16 mma, f32 accum).
// CTA tile 128x256, BK=64, 2 stages, 256 threads, warp tile 64x64.
// ---------------------------------------------------------------------------
#define TM 128
#define TN 256
#define BKQ 64
#define NKCH (N_DIM / BKQ)           // 64
#define RSB 144                      // smem row stride bytes (72 fp16): 16B bank rotation
#define A_BYTES (TM * RSB)           // 18432
#define B_BYTES (TN * RSB)           // 36864
#define OFF_B A_BYTES
#define STAGE_BYTES (A_BYTES + B_BYTES)   // 55296
#define SM_TOTAL (2 * STAGE_BYTES)        // 110592

__device__ __forceinline__ void load_stage(uint32_t st, int bm, int bn, int k0, int tid) {
    // A: 128 rows x 8 chunks(16B) = 1024 chunks, 4/thread
#pragma unroll
    for (int j = 0; j < 4; ++j) {
        int c = tid + j * 256;
        int row = c >> 3, cc = c & 7;
        cp_async16(st + row * RSB + cc * 16,
                   g_xh + (size_t)(bm + row) * N_DIM + k0 + cc * 8);
    }
    // B: 256 rows x 8 chunks = 2048 chunks, 8/thread
#pragma unroll
    for (int j = 0; j < 8; ++j) {
        int c = tid + j * 256;
        int row = c >> 3, cc = c & 7;
        cp_async16(st + OFF_B + row * RSB + cc * 16,
                   g_w + (size_t)(bn + row) * N_DIM + k0 + cc * 8);
    }
}

__global__ __launch_bounds__(256, 1) void tt_gemm_kernel(
    const float* __restrict__ bias, float* __restrict__ out)
{
    extern __shared__ char smem[];
    uint32_t sb = smem_u32(smem);

    int tid = threadIdx.x;
    int lane = tid & 31;
    int wid = tid >> 5;
    int warp_m = wid & 1;        // 64-row slab
    int warp_n = wid >> 1;       // 64-col slab
    int bn = blockIdx.x * TN;
    int bm = blockIdx.y * TM;

    uint32_t stage[2] = {sb, sb + STAGE_BYTES};

    load_stage(stage[0], bm, bn, 0, tid);
    CP_COMMIT();
    load_stage(stage[1], bm, bn, BKQ, tid);
    CP_COMMIT();

    float acc[4][8][4];
#pragma unroll
    for (int mf = 0; mf < 4; ++mf)
#pragma unroll
        for (int nf = 0; nf < 8; ++nf)
#pragma unroll
            for (int e = 0; e < 4; ++e) acc[mf][nf][e] = 0.f;

    uint32_t aoff = (warp_m * 64 + (lane & 15)) * RSB + (lane >> 4) * 16;
    uint32_t boff = (warp_n * 64 + (lane & 7)) * RSB + ((lane >> 3) & 1) * 16;

    for (int kt = 0; kt < NKCH; ++kt) {
        uint32_t st = stage[kt & 1];
        CP_WAIT1();
        __syncthreads();

        uint32_t aB = st + aoff;
        uint32_t bB = st + OFF_B + boff;

#pragma unroll
        for (int ks = 0; ks < 4; ++ks) {
            uint32_t ko = ks * 32;   // 16 fp16 = 32 bytes
            uint32_t a[4][4];
#pragma unroll
            for (int mf = 0; mf < 4; ++mf)
                LDSM_X4(a[mf], aB + mf * 16 * RSB + ko);
#pragma unroll
            for (int nf = 0; nf < 8; ++nf) {
                uint32_t b[2];
                LDSM_X2(b, bB + nf * 8 * RSB + ko);
#pragma unroll
                for (int mf = 0; mf < 4; ++mf)
                    MMA16816(acc[mf][nf], a[mf], b);
            }
        }

        __syncthreads();
        if (kt + 2 < NKCH)
            load_stage(st, bm, bn, (kt + 2) * BKQ, tid);
        CP_COMMIT();
    }
    CP_WAIT0();

    // Epilogue
#pragma unroll
    for (int nf = 0; nf < 8; ++nf) {
        int col = bn + warp_n * 64 + nf * 8 + (lane & 3) * 2;
        float2 bv = *(const float2*)&bias[col];
#pragma unroll
        for (int mf = 0; mf < 4; ++mf) {
            int r0 = bm + warp_m * 64 + mf * 16 + (lane >> 2);
            float2 v0 = make_float2(acc[mf][nf][0] + bv.x, acc[mf][nf][1] + bv.y);
            float2 v1 = make_float2(acc[mf][nf][2] + bv.x, acc[mf][nf][3] + bv.y);
            *(float2*)&out[(size_t)r0 * N_DIM + col] = v0;
            *(float2*)&out[(size_t)(r0 + 8) * N_DIM + col] = v1;
        }
    }
}

// ---------------------------------------------------------------------------
extern "C" void kernel_launch(void* const* d_in, const int* in_sizes, int n_in,
                              void* d_out, int out_size) {
    const float* x     = (const float*)d_in[0];
    const float* core0 = (const float*)d_in[1];
    const float* core1 = (const float*)d_in[2];
    const float* core2 = (const float*)d_in[3];
    const float* core3 = (const float*)d_in[4];
    const float* bias  = (const float*)d_in[5];
    float* out = (float*)d_out;

    cudaFuncSetAttribute(tt_gemm_kernel,
                         cudaFuncAttributeMaxDynamicSharedMemorySize, SM_TOTAL);
    cudaFuncSetAttribute(build_Wt_kernel,
                         cudaFuncAttributeMaxDynamicSharedMemorySize, 81920);

    build_G01t_kernel<<<1024, 256>>>(core0, core1);
    build_G23t_kernel<<<1024, 256>>>(core2, core3);
    build_Wt_kernel<<<1024, 256, 81920>>>();
    convert_x_kernel<<<4096, 256>>>(x);

    dim3 grid(N_DIM / TN, B_DIM / TM);   // (16, 8) = 128 CTAs
    tt_gemm_kernel<<<grid, 256, SM_TOTAL>>>(bias, out);
}

// round 12
// speedup vs baseline: 3.9054x; 1.0127x over previous
#include <cuda_runtime.h>
#include <cuda_fp16.h>
#include <cstdint>

// ===========================================================================
// TTLayer = x @ W + bias, W = dense TT realization, fp16 single-product MMA.
//   G01t[Q][r2][P], G23t[T][r2][S]  (fp32)
//   Wt[out][in] fp16,  x -> fp16
//   out = fp16 mma (f32 accum) + bias, 3-stage cp.async pipeline
// ===========================================================================

#define N_DIM 4096
#define B_DIM 1024

static __device__ float  g_G01t[64 * 64 * 64];          // [Q][r2][P]
static __device__ float  g_G23t[64 * 64 * 64];          // [T][r2][S]
static __device__ __half g_xh[(size_t)B_DIM * N_DIM];   // x fp16
static __device__ __half g_w[(size_t)N_DIM * N_DIM];    // Wt fp16 [out][in]

// ---------------------------------------------------------------------------
__device__ __forceinline__ uint32_t smem_u32(const void* p) {
    uint32_t a;
    asm("{ .reg .u64 t; cvta.to.shared.u64 t, %1; cvt.u32.u64 %0, t; }"
        : "=r"(a) : "l"(p));
    return a;
}
__device__ __forceinline__ void cp_async16(uint32_t dst, const void* src) {
    asm volatile("cp.async.cg.shared.global [%0], [%1], 16;\n" :: "r"(dst), "l"(src));
}
#define CP_COMMIT() asm volatile("cp.async.commit_group;\n" ::: "memory")
#define CP_WAIT1()  asm volatile("cp.async.wait_group 1;\n" ::: "memory")
#define CP_WAIT0()  asm volatile("cp.async.wait_group 0;\n" ::: "memory")

#define LDSM_X4(r, addr) \
    asm volatile("ldmatrix.sync.aligned.m8n8.x4.shared.b16 {%0,%1,%2,%3}, [%4];" \
                 : "=r"((r)[0]), "=r"((r)[1]), "=r"((r)[2]), "=r"((r)[3]) : "r"(addr))
#define LDSM_X2(r, addr) \
    asm volatile("ldmatrix.sync.aligned.m8n8.x2.shared.b16 {%0,%1}, [%2];" \
                 : "=r"((r)[0]), "=r"((r)[1]) : "r"(addr))

#define MMA16816(d, a, b) \
    asm volatile("mma.sync.aligned.m16n8k16.row.col.f32.f16.f16.f32 " \
                 "{%0,%1,%2,%3}, {%4,%5,%6,%7}, {%8,%9}, {%0,%1,%2,%3};" \
                 : "+f"((d)[0]), "+f"((d)[1]), "+f"((d)[2]), "+f"((d)[3]) \
                 : "r"((a)[0]), "r"((a)[1]), "r"((a)[2]), "r"((a)[3]), \
                   "r"((b)[0]), "r"((b)[1]))

// ---------------------------------------------------------------------------
// Builders: fused G01t + G23t (grid 2048: low half G01t, high half G23t)
// ---------------------------------------------------------------------------
__global__ void build_G_kernel(const float* __restrict__ core0,
                               const float* __restrict__ core1,
                               const float* __restrict__ core2,
                               const float* __restrict__ core3) {
    int gbx = blockIdx.x;
    if (gbx < 1024) {
        int idx = gbx * 256 + threadIdx.x;   // Q*4096 + r2*64 + P
        int P = idx & 63;
        int r2 = (idx >> 6) & 63;
        int Q = idx >> 12;
        int i0 = P >> 3, i1 = P & 7;
        int o0 = Q >> 3, o1 = Q & 7;
        const float* c0 = core0 + (i0 * 8 + o0) * 64;
        const float* c1 = core1 + (i1 * 8 + o1) * 64 + r2;
        float acc = 0.f;
#pragma unroll 16
        for (int r1 = 0; r1 < 64; ++r1)
            acc = fmaf(c0[r1], c1[r1 * 4096], acc);
        g_G01t[idx] = acc;
    } else {
        int idx = (gbx - 1024) * 256 + threadIdx.x;  // T*4096 + r2*64 + S
        int S = idx & 63;
        int r2 = (idx >> 6) & 63;
        int T = idx >> 12;
        int i2 = S >> 3, i3 = S & 7;
        int o2 = T >> 3, o3 = T & 7;
        const float* c2 = core2 + ((r2 * 8 + i2) * 8 + o2) * 64;
        const float* c3 = core3 + i3 * 8 + o3;
        float acc = 0.f;
#pragma unroll 16
        for (int r3 = 0; r3 < 64; ++r3)
            acc = fmaf(c2[r3], c3[r3 * 64], acc);
        g_G23t[idx] = acc;
    }
}

// ---------------------------------------------------------------------------
// build_Wt: block = (Q, group of 4 T). Grid 1024. 8x8 per-thread tiles.
// ---------------------------------------------------------------------------
__global__ __launch_bounds__(256) void build_Wt_kernel() {
    extern __shared__ float sw[];
    float* sA = sw;               // [r2*64 + P]
    float* sB = sw + 64 * 64;     // [r2*256 + tl*64 + S]

    int bx = blockIdx.x;          // 1024
    int Q = bx >> 4, Tg = bx & 15;
    int tid = threadIdx.x;

    const float* gA = g_G01t + Q * 4096;
    for (int e = tid; e < 4096; e += 256) sA[e] = gA[e];
    const float* gB = g_G23t + Tg * 4 * 4096;
    for (int e = tid; e < 16384; e += 256) {
        int tl = e >> 12, r2 = (e >> 6) & 63, S = e & 63;
        sB[r2 * 256 + tl * 64 + S] = gB[tl * 4096 + r2 * 64 + S];
    }
    __syncthreads();

    int p0 = (tid >> 5) * 8;
    int c0 = (tid & 31) * 8;
    int tl = c0 >> 6, S0 = c0 & 63;

    float acc[8][8];
#pragma unroll
    for (int p = 0; p < 8; ++p)
#pragma unroll
        for (int s = 0; s < 8; ++s) acc[p][s] = 0.f;

#pragma unroll 2
    for (int r2 = 0; r2 < 64; ++r2) {
        float4 a0 = *(const float4*)&sA[r2 * 64 + p0];
        float4 a1 = *(const float4*)&sA[r2 * 64 + p0 + 4];
        float4 b0 = *(const float4*)&sB[r2 * 256 + c0];
        float4 b1 = *(const float4*)&sB[r2 * 256 + c0 + 4];
        float ar[8] = {a0.x, a0.y, a0.z, a0.w, a1.x, a1.y, a1.z, a1.w};
        float br[8] = {b0.x, b0.y, b0.z, b0.w, b1.x, b1.y, b1.z, b1.w};
#pragma unroll
        for (int p = 0; p < 8; ++p)
#pragma unroll
            for (int s = 0; s < 8; ++s)
                acc[p][s] = fmaf(ar[p], br[s], acc[p][s]);
    }

    int n = Q * 64 + Tg * 4 + tl;
    __half* wrow = g_w + (size_t)n * N_DIM;
#pragma unroll
    for (int p = 0; p < 8; ++p) {
        __half h[8];
#pragma unroll
        for (int s = 0; s < 8; ++s) h[s] = __float2half_rn(acc[p][s]);
        *(uint4*)&wrow[(p0 + p) * 64 + S0] = *(uint4*)h;
    }
}

__global__ void convert_x_kernel(const float* __restrict__ x) {
    int i4 = (blockIdx.x * blockDim.x + threadIdx.x) * 4;
    float4 v = *(const float4*)(x + i4);
    __half h[4] = {__float2half_rn(v.x), __float2half_rn(v.y),
                   __float2half_rn(v.z), __float2half_rn(v.w)};
    *(uint2*)&g_xh[i4] = *(uint2*)h;
}

// ---------------------------------------------------------------------------
// Apply GEMM: out[1024,4096] = x * Wt^T + bias (fp16 mma, f32 accum).
// CTA tile 128x256, BK=64, 3 stages, 256 threads, warp tile 64x64.
// One __syncthreads per k-iter; load of chunk kt+2 overlaps mma of chunk kt.
// ---------------------------------------------------------------------------
#define TM 128
#define TN 256
#define BKQ 64
#define NKCH (N_DIM / BKQ)           // 64
#define RSB 144                      // row stride bytes: 16B bank rotation
#define A_BYTES (TM * RSB)           // 18432
#define B_BYTES (TN * RSB)           // 36864
#define OFF_B A_BYTES
#define STAGE_BYTES (A_BYTES + B_BYTES)   // 55296
#define NSTAGE 3
#define SM_TOTAL (NSTAGE * STAGE_BYTES)   // 165888

__device__ __forceinline__ void load_stage(uint32_t st, int bm, int bn, int k0, int tid) {
#pragma unroll
    for (int j = 0; j < 4; ++j) {               // A: 1024 16B chunks
        int c = tid + j * 256;
        int row = c >> 3, cc = c & 7;
        cp_async16(st + row * RSB + cc * 16,
                   g_xh + (size_t)(bm + row) * N_DIM + k0 + cc * 8);
    }
#pragma unroll
    for (int j = 0; j < 8; ++j) {               // B: 2048 16B chunks
        int c = tid + j * 256;
        int row = c >> 3, cc = c & 7;
        cp_async16(st + OFF_B + row * RSB + cc * 16,
                   g_w + (size_t)(bn + row) * N_DIM + k0 + cc * 8);
    }
}

__global__ __launch_bounds__(256, 1) void tt_gemm_kernel(
    const float* __restrict__ bias, float* __restrict__ out)
{
    extern __shared__ char smem[];
    uint32_t sb = smem_u32(smem);

    int tid = threadIdx.x;
    int lane = tid & 31;
    int wid = tid >> 5;
    int warp_m = wid & 1;
    int warp_n = wid >> 1;
    int bn = blockIdx.x * TN;
    int bm = blockIdx.y * TM;

    uint32_t stage[NSTAGE] = {sb, sb + STAGE_BYTES, sb + 2 * STAGE_BYTES};

    load_stage(stage[0], bm, bn, 0, tid);
    CP_COMMIT();
    load_stage(stage[1], bm, bn, BKQ, tid);
    CP_COMMIT();

    float acc[4][8][4];
#pragma unroll
    for (int mf = 0; mf < 4; ++mf)
#pragma unroll
        for (int nf = 0; nf < 8; ++nf)
#pragma unroll
            for (int e = 0; e < 4; ++e) acc[mf][nf][e] = 0.f;

    uint32_t aoff = (warp_m * 64 + (lane & 15)) * RSB + (lane >> 4) * 16;
    uint32_t boff = (warp_n * 64 + (lane & 7)) * RSB + ((lane >> 3) & 1) * 16;

    int s = 0;                    // stage of chunk kt
    int sl = 2;                   // stage to load chunk kt+2 into
    for (int kt = 0; kt < NKCH; ++kt) {
        CP_WAIT1();               // chunk kt resident (kt+1 may be in flight)
        __syncthreads();          // all warps done reading stage sl (= chunk kt-1)

        if (kt + 2 < NKCH)
            load_stage(stage[sl], bm, bn, (kt + 2) * BKQ, tid);
        CP_COMMIT();              // overlaps with mma below

        uint32_t aB = stage[s] + aoff;
        uint32_t bB = stage[s] + OFF_B + boff;

#pragma unroll
        for (int ks = 0; ks < 4; ++ks) {
            uint32_t ko = ks * 32;
            uint32_t a[4][4];
#pragma unroll
            for (int mf = 0; mf < 4; ++mf)
                LDSM_X4(a[mf], aB + mf * 16 * RSB + ko);
#pragma unroll
            for (int nf = 0; nf < 8; ++nf) {
                uint32_t b[2];
                LDSM_X2(b, bB + nf * 8 * RSB + ko);
#pragma unroll
                for (int mf = 0; mf < 4; ++mf)
                    MMA16816(acc[mf][nf], a[mf], b);
            }
        }

        s = (s == 2) ? 0 : s + 1;
        sl = (sl == 2) ? 0 : sl + 1;
    }
    CP_WAIT0();

    // Epilogue
#pragma unroll
    for (int nf = 0; nf < 8; ++nf) {
        int col = bn + warp_n * 64 + nf * 8 + (lane & 3) * 2;
        float2 bv = *(const float2*)&bias[col];
#pragma unroll
        for (int mf = 0; mf < 4; ++mf) {
            int r0 = bm + warp_m * 64 + mf * 16 + (lane >> 2);
            float2 v0 = make_float2(acc[mf][nf][0] + bv.x, acc[mf][nf][1] + bv.y);
            float2 v1 = make_float2(acc[mf][nf][2] + bv.x, acc[mf][nf][3] + bv.y);
            *(float2*)&out[(size_t)r0 * N_DIM + col] = v0;
            *(float2*)&out[(size_t)(r0 + 8) * N_DIM + col] = v1;
        }
    }
}

// ---------------------------------------------------------------------------
extern "C" void kernel_launch(void* const* d_in, const int* in_sizes, int n_in,
                              void* d_out, int out_size) {
    const float* x     = (const float*)d_in[0];
    const float* core0 = (const float*)d_in[1];
    const float* core1 = (const float*)d_in[2];
    const float* core2 = (const float*)d_in[3];
    const float* core3 = (const float*)d_in[4];
    const float* bias  = (const float*)d_in[5];
    float* out = (float*)d_out;

    cudaFuncSetAttribute(tt_gemm_kernel,
                         cudaFuncAttributeMaxDynamicSharedMemorySize, SM_TOTAL);
    cudaFuncSetAttribute(build_Wt_kernel,
                         cudaFuncAttributeMaxDynamicSharedMemorySize, 81920);

    build_G_kernel<<<2048, 256>>>(core0, core1, core2, core3);
    build_Wt_kernel<<<1024, 256, 81920>>>();
    convert_x_kernel<<<4096, 256>>>(x);

    dim3 grid(N_DIM / TN, B_DIM / TM);   // (16, 8) = 128 CTAs
    tt_gemm_kernel<<<grid, 256, SM_TOTAL>>>(bias, out);
}

// round 14
// speedup vs baseline: 4.1432x; 1.0609x over previous
#include <cuda_runtime.h>
#include <cuda_fp16.h>
#include <cstdint>

// ===========================================================================
// TTLayer = x @ W + bias, W = dense TT realization.
//   build_G:  G01h[Q][P][r2], G23h[T][S][r2]  (fp16, fp32 math)
//   build_Wt_mma: per (Q,T) 64x64x64 fp16 tensor-core GEMM -> W rows fp16
//   x -> fp16;  apply: fp16 mma (f32 accum) + bias, 3-stage cp.async pipeline
// ===========================================================================

#define N_DIM 4096
#define B_DIM 1024

static __device__ __half g_G01h[64 * 64 * 64];          // [Q][P][r2]
static __device__ __half g_G23h[64 * 64 * 64];          // [T][S][r2]
static __device__ __half g_xh[(size_t)B_DIM * N_DIM];   // x fp16
static __device__ __half g_w[(size_t)N_DIM * N_DIM];    // Wt fp16 [out][in]

// ---------------------------------------------------------------------------
__device__ __forceinline__ uint32_t smem_u32(const void* p) {
    uint32_t a;
    asm("{ .reg .u64 t; cvta.to.shared.u64 t, %1; cvt.u32.u64 %0, t; }"
        : "=r"(a) : "l"(p));
    return a;
}
__device__ __forceinline__ void cp_async16(uint32_t dst, const void* src) {
    asm volatile("cp.async.cg.shared.global [%0], [%1], 16;\n" :: "r"(dst), "l"(src));
}
#define CP_COMMIT() asm volatile("cp.async.commit_group;\n" ::: "memory")
#define CP_WAIT1()  asm volatile("cp.async.wait_group 1;\n" ::: "memory")
#define CP_WAIT0()  asm volatile("cp.async.wait_group 0;\n" ::: "memory")

#define LDSM_X4(r, addr) \
    asm volatile("ldmatrix.sync.aligned.m8n8.x4.shared.b16 {%0,%1,%2,%3}, [%4];" \
                 : "=r"((r)[0]), "=r"((r)[1]), "=r"((r)[2]), "=r"((r)[3]) : "r"(addr))

#define MMA16816(d, a, b) \
    asm volatile("mma.sync.aligned.m16n8k16.row.col.f32.f16.f16.f32 " \
                 "{%0,%1,%2,%3}, {%4,%5,%6,%7}, {%8,%9}, {%0,%1,%2,%3};" \
                 : "+f"((d)[0]), "+f"((d)[1]), "+f"((d)[2]), "+f"((d)[3]) \
                 : "r"((a)[0]), "r"((a)[1]), "r"((a)[2]), "r"((a)[3]), \
                   "r"((b)[0]), "r"((b)[1]))

// ---------------------------------------------------------------------------
// build_G: fused. Low 1024 blocks -> G01h [Q][P][r2]; high -> G23h [T][S][r2].
// ---------------------------------------------------------------------------
__global__ void build_G_kernel(const float* __restrict__ core0,
                               const float* __restrict__ core1,
                               const float* __restrict__ core2,
                               const float* __restrict__ core3) {
    int gbx = blockIdx.x;
    if (gbx < 1024) {
        int idx = gbx * 256 + threadIdx.x;   // Q*4096 + P*64 + r2
        int r2 = idx & 63;
        int P = (idx >> 6) & 63;
        int Q = idx >> 12;
        int i0 = P >> 3, i1 = P & 7;
        int o0 = Q >> 3, o1 = Q & 7;
        const float* c0 = core0 + (i0 * 8 + o0) * 64;          // + r1
        const float* c1 = core1 + (i1 * 8 + o1) * 64 + r2;     // + r1*4096
        float acc = 0.f;
#pragma unroll 16
        for (int r1 = 0; r1 < 64; ++r1)
            acc = fmaf(c0[r1], c1[r1 * 4096], acc);
        g_G01h[idx] = __float2half_rn(acc);
    } else {
        int idx = (gbx - 1024) * 256 + threadIdx.x;  // T*4096 + S*64 + r2
        int r2 = idx & 63;
        int S = (idx >> 6) & 63;
        int T = idx >> 12;
        int i2 = S >> 3, i3 = S & 7;
        int o2 = T >> 3, o3 = T & 7;
        const float* c2 = core2 + ((r2 * 8 + i2) * 8 + o2) * 64;  // + r3
        const float* c3 = core3 + i3 * 8 + o3;                    // + r3*64
        float acc = 0.f;
#pragma unroll 16
        for (int r3 = 0; r3 < 64; ++r3)
            acc = fmaf(c2[r3], c3[r3 * 64], acc);
        g_G23h[idx] = __float2half_rn(acc);
    }
}

// ---------------------------------------------------------------------------
// build_Wt_mma: block = (Q, group of 8 T). Grid 512, 256 threads (8 warps).
// Warp w: C[P][S] = sum_r2 A[P][r2] * B[S][r2] for T = Tg*8 + w,
// writes W row n = Q*64 + T (row-major [P][S] = contiguous 4096 fp16).
// Tile row = 64 halves = 128 B = 8 x16B chunks (cc = c&7, row = c>>3).
// ---------------------------------------------------------------------------
#define WB_RSB 144
#define WB_TILE (64 * WB_RSB)          // 9216 bytes per 64x64 fp16 tile
#define WB_SMEM (9 * WB_TILE)          // A + 8 B tiles = 82944

__global__ __launch_bounds__(256) void build_Wt_mma_kernel() {
    extern __shared__ char swm[];
    uint32_t sb = smem_u32(swm);
    uint32_t sA = sb;
    uint32_t sB0 = sb + WB_TILE;

    int bx = blockIdx.x;          // 512
    int Q = bx >> 3, Tg = bx & 7;
    int tid = threadIdx.x;
    int lane = tid & 31;
    int w = tid >> 5;

    // Load A: 64 rows x 8 x16B chunks = 512, 2/thread
#pragma unroll
    for (int j = 0; j < 2; ++j) {
        int c = tid + j * 256;
        int row = c >> 3, cc = c & 7;
        cp_async16(sA + row * WB_RSB + cc * 16,
                   g_G01h + Q * 4096 + row * 64 + cc * 8);
    }
    // Load B: 8 T tiles x 512 chunks = 4096, 16/thread
#pragma unroll
    for (int j = 0; j < 16; ++j) {
        int c = tid + j * 256;
        int t = c >> 9, rc = c & 511;
        int row = rc >> 3, cc = rc & 7;
        cp_async16(sB0 + t * WB_TILE + row * WB_RSB + cc * 16,
                   g_G23h + (size_t)(Tg * 8 + t) * 4096 + row * 64 + cc * 8);
    }
    CP_COMMIT();
    CP_WAIT0();
    __syncthreads();

    uint32_t sBw = sB0 + w * WB_TILE;

    float acc[4][8][4];
#pragma unroll
    for (int mf = 0; mf < 4; ++mf)
#pragma unroll
        for (int nf = 0; nf < 8; ++nf)
#pragma unroll
            for (int e = 0; e < 4; ++e) acc[mf][nf][e] = 0.f;

    uint32_t aoff = (lane & 15) * WB_RSB + (lane >> 4) * 16;
    uint32_t boff4 = ((lane & 7) + ((lane >> 4) << 3)) * WB_RSB + ((lane >> 3) & 1) * 16;

#pragma unroll
    for (int ks = 0; ks < 4; ++ks) {
        uint32_t ko = ks * 32;
        uint32_t a[4][4], bb[4][4];
#pragma unroll
        for (int mf = 0; mf < 4; ++mf)
            LDSM_X4(a[mf], sA + aoff + mf * 16 * WB_RSB + ko);
#pragma unroll
        for (int j = 0; j < 4; ++j)
            LDSM_X4(bb[j], sBw + boff4 + j * 16 * WB_RSB + ko);
#pragma unroll
        for (int j = 0; j < 4; ++j)
#pragma unroll
            for (int mf = 0; mf < 4; ++mf) {
                MMA16816(acc[mf][2 * j],     a[mf], bb[j]);
                MMA16816(acc[mf][2 * j + 1], a[mf], bb[j] + 2);
            }
    }

    // Store W row n: C[P][S] fp16
    int n = Q * 64 + Tg * 8 + w;
    __half* wrow = g_w + (size_t)n * N_DIM;
#pragma unroll
    for (int nf = 0; nf < 8; ++nf) {
        int s0 = nf * 8 + (lane & 3) * 2;
#pragma unroll
        for (int mf = 0; mf < 4; ++mf) {
            int p0 = mf * 16 + (lane >> 2);
            __half2 v0 = __floats2half2_rn(acc[mf][nf][0], acc[mf][nf][1]);
            __half2 v1 = __floats2half2_rn(acc[mf][nf][2], acc[mf][nf][3]);
            *(__half2*)&wrow[p0 * 64 + s0] = v0;
            *(__half2*)&wrow[(p0 + 8) * 64 + s0] = v1;
        }
    }
}

__global__ void convert_x_kernel(const float* __restrict__ x) {
    int i4 = (blockIdx.x * blockDim.x + threadIdx.x) * 4;
    float4 v = *(const float4*)(x + i4);
    __half h[4] = {__float2half_rn(v.x), __float2half_rn(v.y),
                   __float2half_rn(v.z), __float2half_rn(v.w)};
    *(uint2*)&g_xh[i4] = *(uint2*)h;
}

// ---------------------------------------------------------------------------
// Apply GEMM: out[1024,4096] = x * Wt^T + bias (fp16 mma, f32 accum).
// CTA tile 128x256, BK=64, 3 stages, 256 threads, warp tile 64x64.
// Per ks: 8 LDSM_X4 (A:4, B:4 paired-nf) then 32 MMAs.
// ---------------------------------------------------------------------------
#define TM 128
#define TN 256
#define BKQ 64
#define NKCH (N_DIM / BKQ)           // 64
#define RSB 144
#define A_BYTES (TM * RSB)           // 18432
#define B_BYTES (TN * RSB)           // 36864
#define OFF_B A_BYTES
#define STAGE_BYTES (A_BYTES + B_BYTES)   // 55296
#define NSTAGE 3
#define SM_TOTAL (NSTAGE * STAGE_BYTES)   // 165888

__device__ __forceinline__ void load_stage(uint32_t st, int bm, int bn, int k0, int tid) {
#pragma unroll
    for (int j = 0; j < 4; ++j) {               // A: 1024 16B chunks
        int c = tid + j * 256;
        int row = c >> 3, cc = c & 7;
        cp_async16(st + row * RSB + cc * 16,
                   g_xh + (size_t)(bm + row) * N_DIM + k0 + cc * 8);
    }
#pragma unroll
    for (int j = 0; j < 8; ++j) {               // B: 2048 16B chunks
        int c = tid + j * 256;
        int row = c >> 3, cc = c & 7;
        cp_async16(st + OFF_B + row * RSB + cc * 16,
                   g_w + (size_t)(bn + row) * N_DIM + k0 + cc * 8);
    }
}

__global__ __launch_bounds__(256, 1) void tt_gemm_kernel(
    const float* __restrict__ bias, float* __restrict__ out)
{
    extern __shared__ char smem[];
    uint32_t sb = smem_u32(smem);

    int tid = threadIdx.x;
    int lane = tid & 31;
    int wid = tid >> 5;
    int warp_m = wid & 1;
    int warp_n = wid >> 1;
    int bn = blockIdx.x * TN;
    int bm = blockIdx.y * TM;

    uint32_t stage[NSTAGE] = {sb, sb + STAGE_BYTES, sb + 2 * STAGE_BYTES};

    load_stage(stage[0], bm, bn, 0, tid);
    CP_COMMIT();
    load_stage(stage[1], bm, bn, BKQ, tid);
    CP_COMMIT();

    float acc[4][8][4];
#pragma unroll
    for (int mf = 0; mf < 4; ++mf)
#pragma unroll
        for (int nf = 0; nf < 8; ++nf)
#pragma unroll
            for (int e = 0; e < 4; ++e) acc[mf][nf][e] = 0.f;

    uint32_t aoff = (warp_m * 64 + (lane & 15)) * RSB + (lane >> 4) * 16;
    uint32_t boff4 = (warp_n * 64 + (lane & 7) + ((lane >> 4) << 3)) * RSB
                     + ((lane >> 3) & 1) * 16;

    int s = 0;
    int sl = 2;
    for (int kt = 0; kt < NKCH; ++kt) {
        CP_WAIT1();
        __syncthreads();

        if (kt + 2 < NKCH)
            load_stage(stage[sl], bm, bn, (kt + 2) * BKQ, tid);
        CP_COMMIT();

        uint32_t aB = stage[s] + aoff;
        uint32_t bB = stage[s] + OFF_B + boff4;

#pragma unroll
        for (int ks = 0; ks < 4; ++ks) {
            uint32_t ko = ks * 32;
            uint32_t a[4][4], bb[4][4];
#pragma unroll
            for (int mf = 0; mf < 4; ++mf)
                LDSM_X4(a[mf], aB + mf * 16 * RSB + ko);
#pragma unroll
            for (int j = 0; j < 4; ++j)
                LDSM_X4(bb[j], bB + j * 16 * RSB + ko);
#pragma unroll
            for (int j = 0; j < 4; ++j)
#pragma unroll
                for (int mf = 0; mf < 4; ++mf) {
                    MMA16816(acc[mf][2 * j],     a[mf], bb[j]);
                    MMA16816(acc[mf][2 * j + 1], a[mf], bb[j] + 2);
                }
        }

        s = (s == 2) ? 0 : s + 1;
        sl = (sl == 2) ? 0 : sl + 1;
    }
    CP_WAIT0();

    // Epilogue
#pragma unroll
    for (int nf = 0; nf < 8; ++nf) {
        int col = bn + warp_n * 64 + nf * 8 + (lane & 3) * 2;
        float2 bv = *(const float2*)&bias[col];
#pragma unroll
        for (int mf = 0; mf < 4; ++mf) {
            int r0 = bm + warp_m * 64 + mf * 16 + (lane >> 2);
            float2 v0 = make_float2(acc[mf][nf][0] + bv.x, acc[mf][nf][1] + bv.y);
            float2 v1 = make_float2(acc[mf][nf][2] + bv.x, acc[mf][nf][3] + bv.y);
            *(float2*)&out[(size_t)r0 * N_DIM + col] = v0;
            *(float2*)&out[(size_t)(r0 + 8) * N_DIM + col] = v1;
        }
    }
}

// ---------------------------------------------------------------------------
extern "C" void kernel_launch(void* const* d_in, const int* in_sizes, int n_in,
                              void* d_out, int out_size) {
    const float* x     = (const float*)d_in[0];
    const float* core0 = (const float*)d_in[1];
    const float* core1 = (const float*)d_in[2];
    const float* core2 = (const float*)d_in[3];
    const float* core3 = (const float*)d_in[4];
    const float* bias  = (const float*)d_in[5];
    float* out = (float*)d_out;

    cudaFuncSetAttribute(tt_gemm_kernel,
                         cudaFuncAttributeMaxDynamicSharedMemorySize, SM_TOTAL);
    cudaFuncSetAttribute(build_Wt_mma_kernel,
                         cudaFuncAttributeMaxDynamicSharedMemorySize, WB_SMEM);

    build_G_kernel<<<2048, 256>>>(core0, core1, core2, core3);
    build_Wt_mma_kernel<<<512, 256, WB_SMEM>>>();
    convert_x_kernel<<<4096, 256>>>(x);

    dim3 grid(N_DIM / TN, B_DIM / TM);   // (16, 8) = 128 CTAs
    tt_gemm_kernel<<<grid, 256, SM_TOTAL>>>(bias, out);
}

// round 15
// speedup vs baseline: 4.1479x; 1.0011x over previous
#include <cuda_runtime.h>
#include <cuda_fp16.h>
#include <cstdint>

// ===========================================================================
// TTLayer = x @ W + bias, W = dense TT realization.
//   build_G:  G01h[Q][P][r2], G23h[T][S][r2]  (fp16, fp32 math)
//   build_Wt_mma: per (Q,T) 64x64x64 fp16 tensor-core GEMM -> W rows fp16
//   x -> fp16;  apply: fp16 mma, 128x128 CTA tile, 2 CTAs/SM, 3-stage pipe
// ===========================================================================

#define N_DIM 4096
#define B_DIM 1024

static __device__ __half g_G01h[64 * 64 * 64];          // [Q][P][r2]
static __device__ __half g_G23h[64 * 64 * 64];          // [T][S][r2]
static __device__ __half g_xh[(size_t)B_DIM * N_DIM];   // x fp16
static __device__ __half g_w[(size_t)N_DIM * N_DIM];    // Wt fp16 [out][in]

// ---------------------------------------------------------------------------
__device__ __forceinline__ uint32_t smem_u32(const void* p) {
    uint32_t a;
    asm("{ .reg .u64 t; cvta.to.shared.u64 t, %1; cvt.u32.u64 %0, t; }"
        : "=r"(a) : "l"(p));
    return a;
}
__device__ __forceinline__ void cp_async16(uint32_t dst, const void* src) {
    asm volatile("cp.async.cg.shared.global [%0], [%1], 16;\n" :: "r"(dst), "l"(src));
}
#define CP_COMMIT() asm volatile("cp.async.commit_group;\n" ::: "memory")
#define CP_WAIT1()  asm volatile("cp.async.wait_group 1;\n" ::: "memory")
#define CP_WAIT0()  asm volatile("cp.async.wait_group 0;\n" ::: "memory")

#define LDSM_X4(r, addr) \
    asm volatile("ldmatrix.sync.aligned.m8n8.x4.shared.b16 {%0,%1,%2,%3}, [%4];" \
                 : "=r"((r)[0]), "=r"((r)[1]), "=r"((r)[2]), "=r"((r)[3]) : "r"(addr))

#define MMA16816(d, a, b) \
    asm volatile("mma.sync.aligned.m16n8k16.row.col.f32.f16.f16.f32 " \
                 "{%0,%1,%2,%3}, {%4,%5,%6,%7}, {%8,%9}, {%0,%1,%2,%3};" \
                 : "+f"((d)[0]), "+f"((d)[1]), "+f"((d)[2]), "+f"((d)[3]) \
                 : "r"((a)[0]), "r"((a)[1]), "r"((a)[2]), "r"((a)[3]), \
                   "r"((b)[0]), "r"((b)[1]))

// ---------------------------------------------------------------------------
// build_G: fused. Low 1024 blocks -> G01h [Q][P][r2]; high -> G23h [T][S][r2].
// ---------------------------------------------------------------------------
__global__ void build_G_kernel(const float* __restrict__ core0,
                               const float* __restrict__ core1,
                               const float* __restrict__ core2,
                               const float* __restrict__ core3) {
    int gbx = blockIdx.x;
    if (gbx < 1024) {
        int idx = gbx * 256 + threadIdx.x;   // Q*4096 + P*64 + r2
        int r2 = idx & 63;
        int P = (idx >> 6) & 63;
        int Q = idx >> 12;
        int i0 = P >> 3, i1 = P & 7;
        int o0 = Q >> 3, o1 = Q & 7;
        const float* c0 = core0 + (i0 * 8 + o0) * 64;          // + r1
        const float* c1 = core1 + (i1 * 8 + o1) * 64 + r2;     // + r1*4096
        float acc = 0.f;
#pragma unroll 16
        for (int r1 = 0; r1 < 64; ++r1)
            acc = fmaf(c0[r1], c1[r1 * 4096], acc);
        g_G01h[idx] = __float2half_rn(acc);
    } else {
        int idx = (gbx - 1024) * 256 + threadIdx.x;  // T*4096 + S*64 + r2
        int r2 = idx & 63;
        int S = (idx >> 6) & 63;
        int T = idx >> 12;
        int i2 = S >> 3, i3 = S & 7;
        int o2 = T >> 3, o3 = T & 7;
        const float* c2 = core2 + ((r2 * 8 + i2) * 8 + o2) * 64;  // + r3
        const float* c3 = core3 + i3 * 8 + o3;                    // + r3*64
        float acc = 0.f;
#pragma unroll 16
        for (int r3 = 0; r3 < 64; ++r3)
            acc = fmaf(c2[r3], c3[r3 * 64], acc);
        g_G23h[idx] = __float2half_rn(acc);
    }
}

// ---------------------------------------------------------------------------
// build_Wt_mma: block = (Q, group of 8 T). Grid 512, 256 threads (8 warps).
// ---------------------------------------------------------------------------
#define WB_RSB 144
#define WB_TILE (64 * WB_RSB)          // 9216 bytes per 64x64 fp16 tile
#define WB_SMEM (9 * WB_TILE)          // A + 8 B tiles = 82944

__global__ __launch_bounds__(256) void build_Wt_mma_kernel() {
    extern __shared__ char swm[];
    uint32_t sb = smem_u32(swm);
    uint32_t sA = sb;
    uint32_t sB0 = sb + WB_TILE;

    int bx = blockIdx.x;          // 512
    int Q = bx >> 3, Tg = bx & 7;
    int tid = threadIdx.x;
    int lane = tid & 31;
    int w = tid >> 5;

    // Load A: 64 rows x 8 x16B chunks = 512, 2/thread
#pragma unroll
    for (int j = 0; j < 2; ++j) {
        int c = tid + j * 256;
        int row = c >> 3, cc = c & 7;
        cp_async16(sA + row * WB_RSB + cc * 16,
                   g_G01h + Q * 4096 + row * 64 + cc * 8);
    }
    // Load B: 8 T tiles x 512 chunks = 4096, 16/thread
#pragma unroll
    for (int j = 0; j < 16; ++j) {
        int c = tid + j * 256;
        int t = c >> 9, rc = c & 511;
        int row = rc >> 3, cc = rc & 7;
        cp_async16(sB0 + t * WB_TILE + row * WB_RSB + cc * 16,
                   g_G23h + (size_t)(Tg * 8 + t) * 4096 + row * 64 + cc * 8);
    }
    CP_COMMIT();
    CP_WAIT0();
    __syncthreads();

    uint32_t sBw = sB0 + w * WB_TILE;

    float acc[4][8][4];
#pragma unroll
    for (int mf = 0; mf < 4; ++mf)
#pragma unroll
        for (int nf = 0; nf < 8; ++nf)
#pragma unroll
            for (int e = 0; e < 4; ++e) acc[mf][nf][e] = 0.f;

    uint32_t aoff = (lane & 15) * WB_RSB + (lane >> 4) * 16;
    uint32_t boff4 = ((lane & 7) + ((lane >> 4) << 3)) * WB_RSB + ((lane >> 3) & 1) * 16;

#pragma unroll
    for (int ks = 0; ks < 4; ++ks) {
        uint32_t ko = ks * 32;
        uint32_t a[4][4], bb[4][4];
#pragma unroll
        for (int mf = 0; mf < 4; ++mf)
            LDSM_X4(a[mf], sA + aoff + mf * 16 * WB_RSB + ko);
#pragma unroll
        for (int j = 0; j < 4; ++j)
            LDSM_X4(bb[j], sBw + boff4 + j * 16 * WB_RSB + ko);
#pragma unroll
        for (int j = 0; j < 4; ++j)
#pragma unroll
            for (int mf = 0; mf < 4; ++mf) {
                MMA16816(acc[mf][2 * j],     a[mf], bb[j]);
                MMA16816(acc[mf][2 * j + 1], a[mf], bb[j] + 2);
            }
    }

    // Store W row n: C[P][S] fp16
    int n = Q * 64 + Tg * 8 + w;
    __half* wrow = g_w + (size_t)n * N_DIM;
#pragma unroll
    for (int nf = 0; nf < 8; ++nf) {
        int s0 = nf * 8 + (lane & 3) * 2;
#pragma unroll
        for (int mf = 0; mf < 4; ++mf) {
            int p0 = mf * 16 + (lane >> 2);
            __half2 v0 = __floats2half2_rn(acc[mf][nf][0], acc[mf][nf][1]);
            __half2 v1 = __floats2half2_rn(acc[mf][nf][2], acc[mf][nf][3]);
            *(__half2*)&wrow[p0 * 64 + s0] = v0;
            *(__half2*)&wrow[(p0 + 8) * 64 + s0] = v1;
        }
    }
}

__global__ void convert_x_kernel(const float* __restrict__ x) {
    int i4 = (blockIdx.x * blockDim.x + threadIdx.x) * 4;
    float4 v = *(const float4*)(x + i4);
    __half h[4] = {__float2half_rn(v.x), __float2half_rn(v.y),
                   __float2half_rn(v.z), __float2half_rn(v.w)};
    *(uint2*)&g_xh[i4] = *(uint2*)h;
}

// ---------------------------------------------------------------------------
// Apply GEMM: out[1024,4096] = x * Wt^T + bias (fp16 mma, f32 accum).
// CTA tile 128x128, BK=64, 3 stages, 256 threads, warp tile 64x32.
// 2 CTAs/SM (108 KB smem, <=128 regs) -> 4 warps/SMSP for latency hiding.
// ---------------------------------------------------------------------------
#define TM 128
#define TN 128
#define BKQ 64
#define NKCH (N_DIM / BKQ)           // 64
#define RSB 144
#define A_BYTES (TM * RSB)           // 18432
#define B_BYTES (TN * RSB)           // 18432
#define OFF_B A_BYTES
#define STAGE_BYTES (A_BYTES + B_BYTES)   // 36864
#define NSTAGE 3
#define SM_TOTAL (NSTAGE * STAGE_BYTES)   // 110592

__device__ __forceinline__ void load_stage(uint32_t st, int bm, int bn, int k0, int tid) {
#pragma unroll
    for (int j = 0; j < 4; ++j) {               // A: 1024 16B chunks
        int c = tid + j * 256;
        int row = c >> 3, cc = c & 7;
        cp_async16(st + row * RSB + cc * 16,
                   g_xh + (size_t)(bm + row) * N_DIM + k0 + cc * 8);
    }
#pragma unroll
    for (int j = 0; j < 4; ++j) {               // B: 1024 16B chunks
        int c = tid + j * 256;
        int row = c >> 3, cc = c & 7;
        cp_async16(st + OFF_B + row * RSB + cc * 16,
                   g_w + (size_t)(bn + row) * N_DIM + k0 + cc * 8);
    }
}

__global__ __launch_bounds__(256, 2) void tt_gemm_kernel(
    const float* __restrict__ bias, float* __restrict__ out)
{
    extern __shared__ char smem[];
    uint32_t sb = smem_u32(smem);

    int tid = threadIdx.x;
    int lane = tid & 31;
    int wid = tid >> 5;
    int warp_m = wid & 1;        // 64-row slab
    int warp_n = wid >> 1;       // 0..3 -> 32-col slab
    int bn = blockIdx.x * TN;
    int bm = blockIdx.y * TM;

    uint32_t stage[NSTAGE] = {sb, sb + STAGE_BYTES, sb + 2 * STAGE_BYTES};

    load_stage(stage[0], bm, bn, 0, tid);
    CP_COMMIT();
    load_stage(stage[1], bm, bn, BKQ, tid);
    CP_COMMIT();

    float acc[4][4][4];
#pragma unroll
    for (int mf = 0; mf < 4; ++mf)
#pragma unroll
        for (int nf = 0; nf < 4; ++nf)
#pragma unroll
            for (int e = 0; e < 4; ++e) acc[mf][nf][e] = 0.f;

    uint32_t aoff = (warp_m * 64 + (lane & 15)) * RSB + (lane >> 4) * 16;
    uint32_t boff4 = (warp_n * 32 + (lane & 7) + ((lane >> 4) << 3)) * RSB
                     + ((lane >> 3) & 1) * 16;

    int s = 0;
    int sl = 2;
    for (int kt = 0; kt < NKCH; ++kt) {
        CP_WAIT1();
        __syncthreads();

        if (kt + 2 < NKCH)
            load_stage(stage[sl], bm, bn, (kt + 2) * BKQ, tid);
        CP_COMMIT();

        uint32_t aB = stage[s] + aoff;
        uint32_t bB = stage[s] + OFF_B + boff4;

#pragma unroll
        for (int ks = 0; ks < 4; ++ks) {
            uint32_t ko = ks * 32;
            uint32_t a[4][4], bb[2][4];
#pragma unroll
            for (int mf = 0; mf < 4; ++mf)
                LDSM_X4(a[mf], aB + mf * 16 * RSB + ko);
#pragma unroll
            for (int j = 0; j < 2; ++j)
                LDSM_X4(bb[j], bB + j * 16 * RSB + ko);
#pragma unroll
            for (int j = 0; j < 2; ++j)
#pragma unroll
                for (int mf = 0; mf < 4; ++mf) {
                    MMA16816(acc[mf][2 * j],     a[mf], bb[j]);
                    MMA16816(acc[mf][2 * j + 1], a[mf], bb[j] + 2);
                }
        }

        s = (s == 2) ? 0 : s + 1;
        sl = (sl == 2) ? 0 : sl + 1;
    }
    CP_WAIT0();

    // Epilogue
#pragma unroll
    for (int nf = 0; nf < 4; ++nf) {
        int col = bn + warp_n * 32 + nf * 8 + (lane & 3) * 2;
        float2 bv = *(const float2*)&bias[col];
#pragma unroll
        for (int mf = 0; mf < 4; ++mf) {
            int r0 = bm + warp_m * 64 + mf * 16 + (lane >> 2);
            float2 v0 = make_float2(acc[mf][nf][0] + bv.x, acc[mf][nf][1] + bv.y);
            float2 v1 = make_float2(acc[mf][nf][2] + bv.x, acc[mf][nf][3] + bv.y);
            *(float2*)&out[(size_t)r0 * N_DIM + col] = v0;
            *(float2*)&out[(size_t)(r0 + 8) * N_DIM + col] = v1;
        }
    }
}

// ---------------------------------------------------------------------------
extern "C" void kernel_launch(void* const* d_in, const int* in_sizes, int n_in,
                              void* d_out, int out_size) {
    const float* x     = (const float*)d_in[0];
    const float* core0 = (const float*)d_in[1];
    const float* core1 = (const float*)d_in[2];
    const float* core2 = (const float*)d_in[3];
    const float* core3 = (const float*)d_in[4];
    const float* bias  = (const float*)d_in[5];
    float* out = (float*)d_out;

    cudaFuncSetAttribute(tt_gemm_kernel,
                         cudaFuncAttributeMaxDynamicSharedMemorySize, SM_TOTAL);
    cudaFuncSetAttribute(build_Wt_mma_kernel,
                         cudaFuncAttributeMaxDynamicSharedMemorySize, WB_SMEM);

    build_G_kernel<<<2048, 256>>>(core0, core1, core2, core3);
    build_Wt_mma_kernel<<<512, 256, WB_SMEM>>>();
    convert_x_kernel<<<4096, 256>>>(x);

    dim3 grid(N_DIM / TN, B_DIM / TM);   // (32, 8) = 256 CTAs, 2/SM
    tt_gemm_kernel<<<grid, 256, SM_TOTAL>>>(bias, out);
}

// round 17
// speedup vs baseline: 5.7965x; 1.3974x over previous
#include <cuda_runtime.h>
#include <cuda_fp16.h>
#include <cstdint>

// ===========================================================================
// TTLayer = x @ W + bias, W = dense TT realization.
//   build_G_tiled: smem-tiled, minimal core traffic -> G01h/G23h (fp16)
//   build_Wt_mma: per (Q,T) 64x64x64 fp16 tensor-core GEMM -> W rows fp16
//   x -> fp16;  apply: fp16 mma, 128x128 CTA tile, 2 CTAs/SM, 3-stage pipe
// ===========================================================================

#define N_DIM 4096
#define B_DIM 1024

static __device__ __half g_G01h[64 * 64 * 64];          // [Q][P][r2]
static __device__ __half g_G23h[64 * 64 * 64];          // [T][S][r2]
static __device__ __half g_xh[(size_t)B_DIM * N_DIM];   // x fp16
static __device__ __half g_w[(size_t)N_DIM * N_DIM];    // Wt fp16 [out][in]

// ---------------------------------------------------------------------------
__device__ __forceinline__ uint32_t smem_u32(const void* p) {
    uint32_t a;
    asm("{ .reg .u64 t; cvta.to.shared.u64 t, %1; cvt.u32.u64 %0, t; }"
        : "=r"(a) : "l"(p));
    return a;
}
__device__ __forceinline__ void cp_async16(uint32_t dst, const void* src) {
    asm volatile("cp.async.cg.shared.global [%0], [%1], 16;\n" :: "r"(dst), "l"(src));
}
#define CP_COMMIT() asm volatile("cp.async.commit_group;\n" ::: "memory")
#define CP_WAIT1()  asm volatile("cp.async.wait_group 1;\n" ::: "memory")
#define CP_WAIT0()  asm volatile("cp.async.wait_group 0;\n" ::: "memory")

#define LDSM_X4(r, addr) \
    asm volatile("ldmatrix.sync.aligned.m8n8.x4.shared.b16 {%0,%1,%2,%3}, [%4];" \
                 : "=r"((r)[0]), "=r"((r)[1]), "=r"((r)[2]), "=r"((r)[3]) : "r"(addr))

#define MMA16816(d, a, b) \
    asm volatile("mma.sync.aligned.m16n8k16.row.col.f32.f16.f16.f32 " \
                 "{%0,%1,%2,%3}, {%4,%5,%6,%7}, {%8,%9}, {%0,%1,%2,%3};" \
                 : "+f"((d)[0]), "+f"((d)[1]), "+f"((d)[2]), "+f"((d)[3]) \
                 : "r"((a)[0]), "r"((a)[1]), "r"((a)[2]), "r"((a)[3]), \
                   "r"((b)[0]), "r"((b)[1]))

// ---------------------------------------------------------------------------
// build_G_tiled: 128 blocks.
//  b < 64:  G01 mode, (i1,o1) = (b&7, b>>3).
//    sX = core0 (16KB), sY[r1*64+r2] = core1[r1*4096 + (i1*8+o1)*64 + r2].
//    out[m=(i0*8+o0)][r2] = sum_r1 sX[m*64+r1]*sY[r1*64+r2]
//    -> g_G01h[(o0*8+o1)*4096 + (i0*8+i1)*64 + r2]
//  b >= 64: G23 mode, r2 = b-64.
//    sX = core2 + r2*4096 (16KB contiguous: [s2=(i2*8+o2)][r3]), sY = core3.
//    out[T=(o2*8+o3)][S=(i2*8+i3)] = sum_r3 sX[(i2*8+o2)*64+r3]*sY[r3*64+i3*8+o3]
//    -> g_G23h[T*4096 + S*64 + r2]
// Math identical (same loop order) to previous build_G -> bit-identical G.
// ---------------------------------------------------------------------------
__global__ __launch_bounds__(256) void build_G_tiled_kernel(
    const float* __restrict__ core0, const float* __restrict__ core1,
    const float* __restrict__ core2, const float* __restrict__ core3)
{
    __shared__ float sX[4096];
    __shared__ float sY[4096];
    int b = blockIdx.x;
    int tid = threadIdx.x;

    if (b < 64) {
        int i1 = b & 7, o1 = b >> 3;
#pragma unroll
        for (int j = 0; j < 16; ++j) {
            int e = tid + j * 256;
            sX[e] = core0[e];
            int r1 = e >> 6, r2 = e & 63;
            sY[e] = core1[r1 * 4096 + (i1 * 8 + o1) * 64 + r2];
        }
        __syncthreads();

        int m0 = (tid >> 4) * 4;     // over (i0*8+o0); aligned 4 => i0 const
        int r20 = (tid & 15) * 4;
        float acc[4][4];
#pragma unroll
        for (int u = 0; u < 4; ++u)
#pragma unroll
            for (int v = 0; v < 4; ++v) acc[u][v] = 0.f;

        for (int r1 = 0; r1 < 64; ++r1) {
            float a0 = sX[(m0 + 0) * 64 + r1];
            float a1 = sX[(m0 + 1) * 64 + r1];
            float a2 = sX[(m0 + 2) * 64 + r1];
            float a3 = sX[(m0 + 3) * 64 + r1];
            float4 bv = *(const float4*)&sY[r1 * 64 + r20];
            float br[4] = {bv.x, bv.y, bv.z, bv.w};
            float ar[4] = {a0, a1, a2, a3};
#pragma unroll
            for (int u = 0; u < 4; ++u)
#pragma unroll
                for (int v = 0; v < 4; ++v)
                    acc[u][v] = fmaf(ar[u], br[v], acc[u][v]);
        }

#pragma unroll
        for (int u = 0; u < 4; ++u) {
            int m = m0 + u;
            int i0 = m >> 3, o0 = m & 7;
            size_t base = (size_t)(o0 * 8 + o1) * 4096 + (i0 * 8 + i1) * 64 + r20;
            __half2 h0 = __floats2half2_rn(acc[u][0], acc[u][1]);
            __half2 h1 = __floats2half2_rn(acc[u][2], acc[u][3]);
            *(__half2*)&g_G01h[base] = h0;
            *(__half2*)&g_G01h[base + 2] = h1;
        }
    } else {
        int r2 = b - 64;
        const float* c2s = core2 + r2 * 4096;
#pragma unroll
        for (int j = 0; j < 16; ++j) {
            int e = tid + j * 256;
            sX[e] = c2s[e];
            sY[e] = core3[e];
        }
        __syncthreads();

        int T0 = (tid >> 4) * 4;     // aligned 4 => o2 = T0>>3 const
        int S0 = (tid & 15) * 4;     // aligned 4 => i2 = S0>>3 const
        int o2 = T0 >> 3, o3_0 = T0 & 7;
        int i2 = S0 >> 3, i3_0 = S0 & 7;
        float acc[4][4];             // [ti][si]
#pragma unroll
        for (int u = 0; u < 4; ++u)
#pragma unroll
            for (int v = 0; v < 4; ++v) acc[u][v] = 0.f;

        for (int r3 = 0; r3 < 64; ++r3) {
            float a = sX[(i2 * 8 + o2) * 64 + r3];
#pragma unroll
            for (int si = 0; si < 4; ++si) {
                float4 bv = *(const float4*)&sY[r3 * 64 + (i3_0 + si) * 8 + o3_0];
                acc[0][si] = fmaf(a, bv.x, acc[0][si]);
                acc[1][si] = fmaf(a, bv.y, acc[1][si]);
                acc[2][si] = fmaf(a, bv.z, acc[2][si]);
                acc[3][si] = fmaf(a, bv.w, acc[3][si]);
            }
        }

#pragma unroll
        for (int ti = 0; ti < 4; ++ti)
#pragma unroll
            for (int si = 0; si < 4; ++si) {
                int T = T0 + ti, S = S0 + si;
                g_G23h[(size_t)T * 4096 + S * 64 + r2] =
                    __float2half_rn(acc[ti][si]);
            }
    }
}

// ---------------------------------------------------------------------------
// build_Wt_mma: block = (Q, group of 8 T). Grid 512, 256 threads (8 warps).
// ---------------------------------------------------------------------------
#define WB_RSB 144
#define WB_TILE (64 * WB_RSB)          // 9216 bytes per 64x64 fp16 tile
#define WB_SMEM (9 * WB_TILE)          // A + 8 B tiles = 82944

__global__ __launch_bounds__(256) void build_Wt_mma_kernel() {
    extern __shared__ char swm[];
    uint32_t sb = smem_u32(swm);
    uint32_t sA = sb;
    uint32_t sB0 = sb + WB_TILE;

    int bx = blockIdx.x;          // 512
    int Q = bx >> 3, Tg = bx & 7;
    int tid = threadIdx.x;
    int lane = tid & 31;
    int w = tid >> 5;

#pragma unroll
    for (int j = 0; j < 2; ++j) {
        int c = tid + j * 256;
        int row = c >> 3, cc = c & 7;
        cp_async16(sA + row * WB_RSB + cc * 16,
                   g_G01h + Q * 4096 + row * 64 + cc * 8);
    }
#pragma unroll
    for (int j = 0; j < 16; ++j) {
        int c = tid + j * 256;
        int t = c >> 9, rc = c & 511;
        int row = rc >> 3, cc = rc & 7;
        cp_async16(sB0 + t * WB_TILE + row * WB_RSB + cc * 16,
                   g_G23h + (size_t)(Tg * 8 + t) * 4096 + row * 64 + cc * 8);
    }
    CP_COMMIT();
    CP_WAIT0();
    __syncthreads();

    uint32_t sBw = sB0 + w * WB_TILE;

    float acc[4][8][4];
#pragma unroll
    for (int mf = 0; mf < 4; ++mf)
#pragma unroll
        for (int nf = 0; nf < 8; ++nf)
#pragma unroll
            for (int e = 0; e < 4; ++e) acc[mf][nf][e] = 0.f;

    uint32_t aoff = (lane & 15) * WB_RSB + (lane >> 4) * 16;
    uint32_t boff4 = ((lane & 7) + ((lane >> 4) << 3)) * WB_RSB + ((lane >> 3) & 1) * 16;

#pragma unroll
    for (int ks = 0; ks < 4; ++ks) {
        uint32_t ko = ks * 32;
        uint32_t a[4][4], bb[4][4];
#pragma unroll
        for (int mf = 0; mf < 4; ++mf)
            LDSM_X4(a[mf], sA + aoff + mf * 16 * WB_RSB + ko);
#pragma unroll
        for (int j = 0; j < 4; ++j)
            LDSM_X4(bb[j], sBw + boff4 + j * 16 * WB_RSB + ko);
#pragma unroll
        for (int j = 0; j < 4; ++j)
#pragma unroll
            for (int mf = 0; mf < 4; ++mf) {
                MMA16816(acc[mf][2 * j],     a[mf], bb[j]);
                MMA16816(acc[mf][2 * j + 1], a[mf], bb[j] + 2);
            }
    }

    int n = Q * 64 + Tg * 8 + w;
    __half* wrow = g_w + (size_t)n * N_DIM;
#pragma unroll
    for (int nf = 0; nf < 8; ++nf) {
        int s0 = nf * 8 + (lane & 3) * 2;
#pragma unroll
        for (int mf = 0; mf < 4; ++mf) {
            int p0 = mf * 16 + (lane >> 2);
            __half2 v0 = __floats2half2_rn(acc[mf][nf][0], acc[mf][nf][1]);
            __half2 v1 = __floats2half2_rn(acc[mf][nf][2], acc[mf][nf][3]);
            *(__half2*)&wrow[p0 * 64 + s0] = v0;
            *(__half2*)&wrow[(p0 + 8) * 64 + s0] = v1;
        }
    }
}

__global__ void convert_x_kernel(const float* __restrict__ x) {
    int i4 = (blockIdx.x * blockDim.x + threadIdx.x) * 4;
    float4 v = *(const float4*)(x + i4);
    __half h[4] = {__float2half_rn(v.x), __float2half_rn(v.y),
                   __float2half_rn(v.z), __float2half_rn(v.w)};
    *(uint2*)&g_xh[i4] = *(uint2*)h;
}

// ---------------------------------------------------------------------------
// Apply GEMM: out[1024,4096] = x * Wt^T + bias (fp16 mma, f32 accum).
// CTA tile 128x128, BK=64, 3 stages, 256 threads, warp tile 64x32, 2 CTAs/SM.
// ---------------------------------------------------------------------------
#define TM 128
#define TN 128
#define BKQ 64
#define NKCH (N_DIM / BKQ)           // 64
#define RSB 144
#define A_BYTES (TM * RSB)           // 18432
#define B_BYTES (TN * RSB)           // 18432
#define OFF_B A_BYTES
#define STAGE_BYTES (A_BYTES + B_BYTES)   // 36864
#define NSTAGE 3
#define SM_TOTAL (NSTAGE * STAGE_BYTES)   // 110592

__device__ __forceinline__ void load_stage(uint32_t st, int bm, int bn, int k0, int tid) {
#pragma unroll
    for (int j = 0; j < 4; ++j) {               // A: 1024 16B chunks
        int c = tid + j * 256;
        int row = c >> 3, cc = c & 7;
        cp_async16(st + row * RSB + cc * 16,
                   g_xh + (size_t)(bm + row) * N_DIM + k0 + cc * 8);
    }
#pragma unroll
    for (int j = 0; j < 4; ++j) {               // B: 1024 16B chunks
        int c = tid + j * 256;
        int row = c >> 3, cc = c & 7;
        cp_async16(st + OFF_B + row * RSB + cc * 16,
                   g_w + (size_t)(bn + row) * N_DIM + k0 + cc * 8);
    }
}

__global__ __launch_bounds__(256, 2) void tt_gemm_kernel(
    const float* __restrict__ bias, float* __restrict__ out)
{
    extern __shared__ char smem[];
    uint32_t sb = smem_u32(smem);

    int tid = threadIdx.x;
    int lane = tid & 31;
    int wid = tid >> 5;
    int warp_m = wid & 1;
    int warp_n = wid >> 1;
    int bn = blockIdx.x * TN;
    int bm = blockIdx.y * TM;

    uint32_t stage[NSTAGE] = {sb, sb + STAGE_BYTES, sb + 2 * STAGE_BYTES};

    load_stage(stage[0], bm, bn, 0, tid);
    CP_COMMIT();
    load_stage(stage[1], bm, bn, BKQ, tid);
    CP_COMMIT();

    float acc[4][4][4];
#pragma unroll
    for (int mf = 0; mf < 4; ++mf)
#pragma unroll
        for (int nf = 0; nf < 4; ++nf)
#pragma unroll
            for (int e = 0; e < 4; ++e) acc[mf][nf][e] = 0.f;

    uint32_t aoff = (warp_m * 64 + (lane & 15)) * RSB + (lane >> 4) * 16;
    uint32_t boff4 = (warp_n * 32 + (lane & 7) + ((lane >> 4) << 3)) * RSB
                     + ((lane >> 3) & 1) * 16;

    int s = 0;
    int sl = 2;
    for (int kt = 0; kt < NKCH; ++kt) {
        CP_WAIT1();
        __syncthreads();

        if (kt + 2 < NKCH)
            load_stage(stage[sl], bm, bn, (kt + 2) * BKQ, tid);
        CP_COMMIT();

        uint32_t aB = stage[s] + aoff;
        uint32_t bB = stage[s] + OFF_B + boff4;

#pragma unroll
        for (int ks = 0; ks < 4; ++ks) {
            uint32_t ko = ks * 32;
            uint32_t a[4][4], bb[2][4];
#pragma unroll
            for (int mf = 0; mf < 4; ++mf)
                LDSM_X4(a[mf], aB + mf * 16 * RSB + ko);
#pragma unroll
            for (int j = 0; j < 2; ++j)
                LDSM_X4(bb[j], bB + j * 16 * RSB + ko);
#pragma unroll
            for (int j = 0; j < 2; ++j)
#pragma unroll
                for (int mf = 0; mf < 4; ++mf) {
                    MMA16816(acc[mf][2 * j],     a[mf], bb[j]);
                    MMA16816(acc[mf][2 * j + 1], a[mf], bb[j] + 2);
                }
        }

        s = (s == 2) ? 0 : s + 1;
        sl = (sl == 2) ? 0 : sl + 1;
    }
    CP_WAIT0();

    // Epilogue
#pragma unroll
    for (int nf = 0; nf < 4; ++nf) {
        int col = bn + warp_n * 32 + nf * 8 + (lane & 3) * 2;
        float2 bv = *(const float2*)&bias[col];
#pragma unroll
        for (int mf = 0; mf < 4; ++mf) {
            int r0 = bm + warp_m * 64 + mf * 16 + (lane >> 2);
            float2 v0 = make_float2(acc[mf][nf][0] + bv.x, acc[mf][nf][1] + bv.y);
            float2 v1 = make_float2(acc[mf][nf][2] + bv.x, acc[mf][nf][3] + bv.y);
            *(float2*)&out[(size_t)r0 * N_DIM + col] = v0;
            *(float2*)&out[(size_t)(r0 + 8) * N_DIM + col] = v1;
        }
    }
}

// ---------------------------------------------------------------------------
extern "C" void kernel_launch(void* const* d_in, const int* in_sizes, int n_in,
                              void* d_out, int out_size) {
    const float* x     = (const float*)d_in[0];
    const float* core0 = (const float*)d_in[1];
    const float* core1 = (const float*)d_in[2];
    const float* core2 = (const float*)d_in[3];
    const float* core3 = (const float*)d_in[4];
    const float* bias  = (const float*)d_in[5];
    float* out = (float*)d_out;

    cudaFuncSetAttribute(tt_gemm_kernel,
                         cudaFuncAttributeMaxDynamicSharedMemorySize, SM_TOTAL);
    cudaFuncSetAttribute(build_Wt_mma_kernel,
                         cudaFuncAttributeMaxDynamicSharedMemorySize, WB_SMEM);

    build_G_tiled_kernel<<<128, 256>>>(core0, core1, core2, core3);
    build_Wt_mma_kernel<<<512, 256, WB_SMEM>>>();
    convert_x_kernel<<<4096, 256>>>(x);

    dim3 grid(N_DIM / TN, B_DIM / TM);   // (32, 8) = 256 CTAs, 2/SM
    tt_gemm_kernel<<<grid, 256, SM_TOTAL>>>(bias, out);
}